// round 7
// baseline (speedup 1.0000x reference)
#include <cuda_runtime.h>
#include <cuda_bf16.h>
#include <cstdint>

// ---------------------------------------------------------------------------
// FiSHAttention: B=8, N=1024, dim=p=768, HEAD_DIM=64, K_GLOBAL=4, H_eff=12
//   0) split x, W_qkv, W_v, W_proj into bf16 hi/lo (elementwise)
//   1) Y(h,l) = x @ Wqkv[0:512].T        (HMMA, cp.async, bf16-split epilogue)
//   2) V      = x @ Wv.T                 (HMMA, f32 out)
//   2b) Vt    = transpose+split of V     (per-head [d][j] hi/lo)
//   3) S4     = 0.125 * qg @ kg.T        (HMMA, 32 batched, f32 out)
//   4) attn: combine+exp2 (FMA) + PV on HMMA; ctx written as bf16 hi/lo
//   5) out    = ctx @ Wproj.T + b_proj   (HMMA, f32 out + bias)
// Split-bf16 3-pass everywhere: C = Ah Bh + Ah Bl + Al Bh (~1e-5 rel err).
// ---------------------------------------------------------------------------

#define B_SZ   8
#define N_SEQ  1024
#define DIM    768
#define KG     4
#define HD     64
#define HEFF   12

__device__ float g_V  [B_SZ * N_SEQ * DIM];
__device__ float g_S4 [(size_t)B_SZ * KG * N_SEQ * N_SEQ];
__device__ __nv_bfloat16 g_xh [B_SZ * N_SEQ * DIM], g_xl [B_SZ * N_SEQ * DIM];
__device__ __nv_bfloat16 g_Wqh[DIM * DIM],          g_Wql[DIM * DIM];
__device__ __nv_bfloat16 g_Wvh[DIM * DIM],          g_Wvl[DIM * DIM];
__device__ __nv_bfloat16 g_Wph[DIM * DIM],          g_Wpl[DIM * DIM];
__device__ __nv_bfloat16 g_Yh [B_SZ * N_SEQ * 512], g_Yl [B_SZ * N_SEQ * 512];
__device__ __nv_bfloat16 g_ch [B_SZ * N_SEQ * DIM], g_cl [B_SZ * N_SEQ * DIM];
__device__ __nv_bfloat16 g_Vth[(size_t)B_SZ * HEFF * HD * N_SEQ];
__device__ __nv_bfloat16 g_Vtl[(size_t)B_SZ * HEFF * HD * N_SEQ];

// ------------------------------ helpers ------------------------------------
__device__ __forceinline__ uint32_t smem_u32(const void* p) {
    uint32_t a;
    asm("{ .reg .u64 t; cvta.to.shared.u64 t, %1; cvt.u32.u64 %0, t; }"
        : "=r"(a) : "l"(p));
    return a;
}
__device__ __forceinline__ void ldsm_x4(uint32_t& r0, uint32_t& r1,
                                        uint32_t& r2, uint32_t& r3, uint32_t addr) {
    asm volatile("ldmatrix.sync.aligned.m8n8.x4.shared.b16 {%0,%1,%2,%3}, [%4];"
        : "=r"(r0), "=r"(r1), "=r"(r2), "=r"(r3) : "r"(addr));
}
__device__ __forceinline__ void mma16816(float* c, const uint32_t* a,
                                         const uint32_t* b) {
    asm volatile("mma.sync.aligned.m16n8k16.row.col.f32.bf16.bf16.f32 "
        "{%0,%1,%2,%3}, {%4,%5,%6,%7}, {%8,%9}, {%0,%1,%2,%3};"
        : "+f"(c[0]), "+f"(c[1]), "+f"(c[2]), "+f"(c[3])
        : "r"(a[0]), "r"(a[1]), "r"(a[2]), "r"(a[3]), "r"(b[0]), "r"(b[1]));
}
__device__ __forceinline__ void cp_async16(uint32_t s, const void* g) {
    asm volatile("cp.async.cg.shared.global [%0], [%1], 16;" :: "r"(s), "l"(g));
}
__device__ __forceinline__ void cp_commit() {
    asm volatile("cp.async.commit_group;" ::: "memory");
}
template<int N> __device__ __forceinline__ void cp_wait() {
    asm volatile("cp.async.wait_group %0;" :: "n"(N) : "memory");
}

__device__ __forceinline__ float fast_exp(float x) {
    x = fmaxf(x, -80.0f);
    const float L2E = 1.4426950408889634f;
    float t  = fmaf(x, L2E, 12582912.0f);
    float nf = t - 12582912.0f;
    int   ni = __float_as_int(t) - 0x4B400000;
    float f  = fmaf(x, L2E, -nf);
    f = fmaf(x, 1.9259629911266175e-8f, f);
    float p;
    p = 1.33335581e-3f;
    p = fmaf(p, f, 9.61812910e-3f);
    p = fmaf(p, f, 5.55041087e-2f);
    p = fmaf(p, f, 2.40226507e-1f);
    p = fmaf(p, f, 6.93147181e-1f);
    p = fmaf(p, f, 1.0f);
    return __int_as_float(__float_as_int(p) + (ni << 23));
}
__device__ __forceinline__ float fast_exp2(float y) {
    y = fmaxf(y, -100.0f);
    float t  = y + 12582912.0f;
    float nf = t - 12582912.0f;
    int   ni = __float_as_int(t) - 0x4B400000;
    float f  = y - nf;
    float p;
    p = 1.33335581e-3f;
    p = fmaf(p, f, 9.61812910e-3f);
    p = fmaf(p, f, 5.55041087e-2f);
    p = fmaf(p, f, 2.40226507e-1f);
    p = fmaf(p, f, 6.93147181e-1f);
    p = fmaf(p, f, 1.0f);
    return __int_as_float(__float_as_int(p) + (ni << 23));
}

// ===========================================================================
// Elementwise f32 -> bf16 hi/lo split.
// ===========================================================================
__global__ __launch_bounds__(256) void split32(
    const float* __restrict__ in, __nv_bfloat16* __restrict__ oh,
    __nv_bfloat16* __restrict__ ol, int n4)
{
    int i = blockIdx.x * 256 + threadIdx.x;
    if (i >= n4) return;
    float4 v = ((const float4*)in)[i];
    __nv_bfloat16 h0 = __float2bfloat16(v.x);
    __nv_bfloat16 h1 = __float2bfloat16(v.y);
    __nv_bfloat16 h2 = __float2bfloat16(v.z);
    __nv_bfloat16 h3 = __float2bfloat16(v.w);
    __nv_bfloat16 l0 = __float2bfloat16(v.x - __bfloat162float(h0));
    __nv_bfloat16 l1 = __float2bfloat16(v.y - __bfloat162float(h1));
    __nv_bfloat16 l2 = __float2bfloat16(v.z - __bfloat162float(h2));
    __nv_bfloat16 l3 = __float2bfloat16(v.w - __bfloat162float(h3));
    uint2 hv, lv;
    hv.x = ((uint32_t)__bfloat16_as_ushort(h1) << 16) | __bfloat16_as_ushort(h0);
    hv.y = ((uint32_t)__bfloat16_as_ushort(h3) << 16) | __bfloat16_as_ushort(h2);
    lv.x = ((uint32_t)__bfloat16_as_ushort(l1) << 16) | __bfloat16_as_ushort(l0);
    lv.y = ((uint32_t)__bfloat16_as_ushort(l3) << 16) | __bfloat16_as_ushort(l2);
    ((uint2*)oh)[i] = hv;
    ((uint2*)ol)[i] = lv;
}

// ===========================================================================
// HMMA TN GEMM on pre-split bf16 operands, cp.async double-buffered.
// C = alpha * A @ B^T; output either f32 C (+bias) or bf16 hi/lo (Ch, Cl).
// CTA 128x128, 8 warps (4x2), warp tile 32x64, BK=32.
// ===========================================================================
#define BKC  32
#define TSTR 40
#define TILEB (128 * TSTR * 2)   // 10240 B per tile
#define GBUF  (4 * TILEB)        // 40960 B per stage
#define GSMEM (2 * GBUF)         // 81920 B

__global__ __launch_bounds__(256) void hmma_gemm_bf16(
    const __nv_bfloat16* __restrict__ Ah, const __nv_bfloat16* __restrict__ Al,
    const __nv_bfloat16* __restrict__ Bh, const __nv_bfloat16* __restrict__ Bl,
    float* __restrict__ C, __nv_bfloat16* __restrict__ Ch,
    __nv_bfloat16* __restrict__ Cl, const float* __restrict__ bias,
    int K, int lda, int ldb, int ldc, float alpha,
    long sAo, long sAi, long sBo, long sBi, long sC, int innerMod)
{
    {
        int z = blockIdx.z;
        int outer = z / innerMod;
        int inner = z - outer * innerMod;
        long ao = (long)outer * sAo + (long)inner * sAi;
        long bo = (long)outer * sBo + (long)inner * sBi;
        Ah += ao; Al += ao; Bh += bo; Bl += bo;
        if (C)  C  += (long)z * sC;
        if (Ch) { Ch += (long)z * sC; Cl += (long)z * sC; }
    }
    const int row0 = blockIdx.y * 128;
    const int col0 = blockIdx.x * 128;

    extern __shared__ char dsm[];
    const uint32_t sbase = smem_u32(dsm);

    const int tid  = threadIdx.x;
    const int wid  = tid >> 5;
    const int lane = tid & 31;
    const int wm   = wid >> 1;
    const int wn   = wid & 1;

    const int a_r = lane & 15;
    const int a_k = (lane >> 4) << 3;
    const int b_r = (lane & 7) + ((lane >> 4) << 3);
    const int b_k = ((lane >> 3) & 1) << 3;

    float acc[2][8][4];
    #pragma unroll
    for (int i = 0; i < 2; i++)
        #pragma unroll
        for (int j = 0; j < 8; j++)
            #pragma unroll
            for (int q = 0; q < 4; q++) acc[i][j][q] = 0.0f;

    const __nv_bfloat16* srcs[4] = {Ah, Al, Bh, Bl};

    auto issue_chunk = [&](int t, uint32_t sb) {
        #pragma unroll
        for (int it = 0; it < 8; it++) {
            const int tile = it >> 1;
            const int rem  = ((it & 1) << 8) + tid;
            const int r = rem >> 2, q = rem & 3;
            const int ld = (tile < 2) ? lda : ldb;
            const int rb = (tile < 2) ? row0 : col0;
            const __nv_bfloat16* g =
                srcs[tile] + (long)(rb + r) * ld + (long)t * BKC + q * 8;
            cp_async16(sb + tile * TILEB + (uint32_t)(r * TSTR + q * 8) * 2, g);
        }
        cp_commit();
    };

    const int nch = K / BKC;
    issue_chunk(0, sbase);

    for (int t = 0; t < nch; t++) {
        const uint32_t cb = sbase + (uint32_t)(t & 1) * GBUF;
        if (t + 1 < nch) {
            issue_chunk(t + 1, sbase + (uint32_t)((t + 1) & 1) * GBUF);
            cp_wait<1>();
        } else {
            cp_wait<0>();
        }
        __syncthreads();

        const uint32_t uAh = cb, uAl = cb + TILEB;
        const uint32_t uBh = cb + 2 * TILEB, uBl = cb + 3 * TILEB;

        #pragma unroll
        for (int ks = 0; ks < 2; ks++) {
            const int k0 = ks * 16;
            const uint32_t aoff = (uint32_t)((wm * 32 + a_r) * TSTR + k0 + a_k) * 2;
            const uint32_t boff = (uint32_t)((wn * 64 + b_r) * TSTR + k0 + b_k) * 2;

            uint32_t af[2][4];
            ldsm_x4(af[0][0], af[0][1], af[0][2], af[0][3], uAh + aoff);
            ldsm_x4(af[1][0], af[1][1], af[1][2], af[1][3], uAh + aoff + 16 * TSTR * 2);

            uint32_t bh[8][2], bl[8][2];
            #pragma unroll
            for (int nb = 0; nb < 4; nb++) {
                ldsm_x4(bh[2*nb][0], bh[2*nb][1], bh[2*nb+1][0], bh[2*nb+1][1],
                        uBh + boff + nb * 16 * TSTR * 2);
                ldsm_x4(bl[2*nb][0], bl[2*nb][1], bl[2*nb+1][0], bl[2*nb+1][1],
                        uBl + boff + nb * 16 * TSTR * 2);
            }
            #pragma unroll
            for (int mf = 0; mf < 2; mf++)
                #pragma unroll
                for (int nf = 0; nf < 8; nf++) {
                    mma16816(acc[mf][nf], af[mf], bh[nf]);
                    mma16816(acc[mf][nf], af[mf], bl[nf]);
                }
            ldsm_x4(af[0][0], af[0][1], af[0][2], af[0][3], uAl + aoff);
            ldsm_x4(af[1][0], af[1][1], af[1][2], af[1][3], uAl + aoff + 16 * TSTR * 2);
            #pragma unroll
            for (int mf = 0; mf < 2; mf++)
                #pragma unroll
                for (int nf = 0; nf < 8; nf++)
                    mma16816(acc[mf][nf], af[mf], bh[nf]);
        }
        __syncthreads();
    }

    // ---- epilogue ----------------------------------------------------------
    const int qrow = lane >> 2;
    const int qcol = (lane & 3) << 1;
    #pragma unroll
    for (int mf = 0; mf < 2; mf++) {
        #pragma unroll
        for (int half = 0; half < 2; half++) {
            long r = row0 + wm * 32 + mf * 16 + half * 8 + qrow;
            #pragma unroll
            for (int nf = 0; nf < 8; nf++) {
                int n = col0 + wn * 64 + nf * 8 + qcol;
                float ox = alpha * acc[mf][nf][half * 2 + 0];
                float oy = alpha * acc[mf][nf][half * 2 + 1];
                if (C) {
                    float2 o;
                    o.x = ox; o.y = oy;
                    if (bias) { o.x += bias[n]; o.y += bias[n + 1]; }
                    *(float2*)&C[r * ldc + n] = o;
                } else {
                    __nv_bfloat16 hx = __float2bfloat16(ox);
                    __nv_bfloat16 hy = __float2bfloat16(oy);
                    __nv_bfloat16 lx = __float2bfloat16(ox - __bfloat162float(hx));
                    __nv_bfloat16 ly = __float2bfloat16(oy - __bfloat162float(hy));
                    uint32_t uh = ((uint32_t)__bfloat16_as_ushort(hy) << 16)
                                | __bfloat16_as_ushort(hx);
                    uint32_t ul = ((uint32_t)__bfloat16_as_ushort(ly) << 16)
                                | __bfloat16_as_ushort(lx);
                    *(uint32_t*)&Ch[r * ldc + n] = uh;
                    *(uint32_t*)&Cl[r * ldc + n] = ul;
                }
            }
        }
    }
}

// ===========================================================================
// V transpose + bf16 hi/lo split (unchanged).
// ===========================================================================
__global__ __launch_bounds__(256) void vconvert(
    const float* __restrict__ V, __nv_bfloat16* __restrict__ Vth,
    __nv_bfloat16* __restrict__ Vtl)
{
    const int j0   = blockIdx.x * 64;
    const int bhid = blockIdx.y;
    const int b    = bhid / HEFF;
    const int h    = bhid - b * HEFF;

    __shared__ float sT[64][68];
    const int tid = threadIdx.x;

    #pragma unroll
    for (int it = 0; it < 4; it++) {
        int e = it * 256 + tid;
        int j = e >> 4, dq = (e & 15) << 2;
        float4 v = *(const float4*)&V[((long)b * N_SEQ + j0 + j) * DIM + h * HD + dq];
        sT[dq + 0][j] = v.x; sT[dq + 1][j] = v.y;
        sT[dq + 2][j] = v.z; sT[dq + 3][j] = v.w;
    }
    __syncthreads();

    const int d = tid >> 2, jseg = (tid & 3) << 4;
    ushort hv[16], lv[16];
    #pragma unroll
    for (int t = 0; t < 16; t++) {
        float f = sT[d][jseg + t];
        __nv_bfloat16 hb = __float2bfloat16(f);
        __nv_bfloat16 lb = __float2bfloat16(f - __bfloat162float(hb));
        hv[t] = __bfloat16_as_ushort(hb);
        lv[t] = __bfloat16_as_ushort(lb);
    }
    size_t dst = ((size_t)bhid * HD + d) * N_SEQ + j0 + jseg;
    *(uint4*)&Vth[dst]     = *(uint4*)&hv[0];
    *(uint4*)&Vth[dst + 8] = *(uint4*)&hv[8];
    *(uint4*)&Vtl[dst]     = *(uint4*)&lv[0];
    *(uint4*)&Vtl[dst + 8] = *(uint4*)&lv[8];
}

// ===========================================================================
// Attention: 2 heads/CTA, PV on HMMA; ctx written as bf16 hi/lo.
// ===========================================================================
#define PBY 9216
#define OFF_V 0
#define OFF_P (4 * PBY)
#define OFF_SUM (8 * PBY)
#define OFF_MIX (OFF_SUM + 512)
#define ATTN_SMEM (OFF_MIX + 64)

__global__ __launch_bounds__(256, 2) void attn_kernel(
    const float* __restrict__ S4,
    const __nv_bfloat16* __restrict__ Vth, const __nv_bfloat16* __restrict__ Vtl,
    const float* __restrict__ mixl,
    __nv_bfloat16* __restrict__ ctxh, __nv_bfloat16* __restrict__ ctxl)
{
    const int ib = blockIdx.x;
    const int hg = blockIdx.y;
    const int b  = blockIdx.z;

    extern __shared__ char sm[];
    const uint32_t sb = smem_u32(sm);
    float* sSum = (float*)(sm + OFF_SUM);
    float* sMix = (float*)(sm + OFF_MIX);

    const int tid  = threadIdx.x;
    const int wid  = tid >> 5;
    const int lane = tid & 31;
    const int wr   = wid >> 1;
    const int wc   = wid & 1;
    const int a_r  = lane & 15;
    const int a_k  = (lane >> 4) << 3;
    const int b_r  = (lane & 7) + ((lane >> 4) << 3);
    const int b_k  = ((lane >> 3) & 1) << 3;

    if (tid < 128) sSum[tid] = 0.0f;
    if (tid < 8) {
        int hh = tid >> 2, k = tid & 3;
        const float* ml = mixl + (hg * 2 + hh) * 4;
        float l0 = ml[0], l1 = ml[1], l2 = ml[2], l3 = ml[3];
        float m  = fmaxf(fmaxf(l0, l1), fmaxf(l2, l3));
        float e0 = fast_exp(l0 - m), e1 = fast_exp(l1 - m);
        float e2 = fast_exp(l2 - m), e3 = fast_exp(l3 - m);
        float s  = e0 + e1 + e2 + e3;
        float mine = (k == 0) ? e0 : (k == 1) ? e1 : (k == 2) ? e2 : e3;
        sMix[hh * 4 + k] = (mine / s) * 1.4426950408889634f;
    }

    const int i0   = ib * 64;
    const int arow = tid >> 2;
    const int aq   = tid & 3;
    const float* S4b = S4 + (long)b * KG * N_SEQ * N_SEQ;
    const long   PL  = (long)N_SEQ * N_SEQ;
    const size_t vbase0 = ((size_t)(b * HEFF + hg * 2 + 0)) * HD * N_SEQ;
    const size_t vbase1 = ((size_t)(b * HEFF + hg * 2 + 1)) * HD * N_SEQ;

    float acc[2][4][4];
    #pragma unroll
    for (int i = 0; i < 2; i++)
        #pragma unroll
        for (int j = 0; j < 4; j++)
            #pragma unroll
            for (int q = 0; q < 4; q++) acc[i][j][q] = 0.0f;

    for (int j0 = 0; j0 < N_SEQ; j0 += 64) {
        __syncthreads();

        #pragma unroll
        for (int it = 0; it < 8; it++) {
            int idx = it * 256 + tid;
            int bufid = idx >> 9;
            int r = (idx >> 3) & 63;
            int q = idx & 7;
            const __nv_bfloat16* src = (bufid & 2) ? Vtl : Vth;
            size_t so = ((bufid & 1) ? vbase1 : vbase0) + (size_t)r * N_SEQ + j0 + q * 8;
            *(uint4*)(sm + OFF_V + bufid * PBY + (r * 72 + q * 8) * 2) =
                *(const uint4*)&src[so];
        }

        {
            const float mx00 = sMix[0], mx01 = sMix[1], mx02 = sMix[2], mx03 = sMix[3];
            const float mx10 = sMix[4], mx11 = sMix[5], mx12 = sMix[6], mx13 = sMix[7];
            const float* base = S4b + (long)(i0 + arow) * N_SEQ + j0 + aq * 16;
            float s0 = 0.0f, s1 = 0.0f;
            #pragma unroll
            for (int c = 0; c < 4; c++) {
                float4 a  = *(const float4*)(base + c * 4);
                float4 p1 = *(const float4*)(base + PL + c * 4);
                float4 p2 = *(const float4*)(base + 2 * PL + c * 4);
                float4 p3 = *(const float4*)(base + 3 * PL + c * 4);
                const uint32_t po = (uint32_t)(arow * 72 + aq * 16 + c * 4) * 2;
                #pragma unroll
                for (int hh = 0; hh < 2; hh++) {
                    float m0 = hh ? mx10 : mx00, m1 = hh ? mx11 : mx01;
                    float m2 = hh ? mx12 : mx02, m3 = hh ? mx13 : mx03;
                    float q0 = fast_exp2(fmaf(m3, p3.x, fmaf(m2, p2.x, fmaf(m1, p1.x, m0 * a.x))));
                    float q1 = fast_exp2(fmaf(m3, p3.y, fmaf(m2, p2.y, fmaf(m1, p1.y, m0 * a.y))));
                    float q2 = fast_exp2(fmaf(m3, p3.z, fmaf(m2, p2.z, fmaf(m1, p1.z, m0 * a.z))));
                    float q3 = fast_exp2(fmaf(m3, p3.w, fmaf(m2, p2.w, fmaf(m1, p1.w, m0 * a.w))));
                    if (hh) s1 += (q0 + q1) + (q2 + q3);
                    else    s0 += (q0 + q1) + (q2 + q3);
                    __nv_bfloat16 h0 = __float2bfloat16(q0);
                    __nv_bfloat16 h1 = __float2bfloat16(q1);
                    __nv_bfloat16 h2 = __float2bfloat16(q2);
                    __nv_bfloat16 h3 = __float2bfloat16(q3);
                    __nv_bfloat16 l0 = __float2bfloat16(q0 - __bfloat162float(h0));
                    __nv_bfloat16 l1 = __float2bfloat16(q1 - __bfloat162float(h1));
                    __nv_bfloat16 l2 = __float2bfloat16(q2 - __bfloat162float(h2));
                    __nv_bfloat16 l3 = __float2bfloat16(q3 - __bfloat162float(h3));
                    uint2 hv, lv;
                    hv.x = ((uint32_t)__bfloat16_as_ushort(h1) << 16) | __bfloat16_as_ushort(h0);
                    hv.y = ((uint32_t)__bfloat16_as_ushort(h3) << 16) | __bfloat16_as_ushort(h2);
                    lv.x = ((uint32_t)__bfloat16_as_ushort(l1) << 16) | __bfloat16_as_ushort(l0);
                    lv.y = ((uint32_t)__bfloat16_as_ushort(l3) << 16) | __bfloat16_as_ushort(l2);
                    *(uint2*)(sm + OFF_P + hh * PBY + po)       = hv;
                    *(uint2*)(sm + OFF_P + (2 + hh) * PBY + po) = lv;
                }
            }
            s0 += __shfl_xor_sync(0xffffffffu, s0, 1);
            s0 += __shfl_xor_sync(0xffffffffu, s0, 2);
            s1 += __shfl_xor_sync(0xffffffffu, s1, 1);
            s1 += __shfl_xor_sync(0xffffffffu, s1, 2);
            if (aq == 0) {
                sSum[arow]      += s0;
                sSum[64 + arow] += s1;
            }
        }
        __syncthreads();

        #pragma unroll
        for (int hh = 0; hh < 2; hh++) {
            const uint32_t uPh = sb + OFF_P + hh * PBY;
            const uint32_t uPl = uPh + 2 * PBY;
            const uint32_t uVh = sb + OFF_V + hh * PBY;
            const uint32_t uVl = uVh + 2 * PBY;
            #pragma unroll
            for (int ks = 0; ks < 4; ks++) {
                const int k0 = ks * 16;
                const uint32_t aoff = (uint32_t)((wr * 16 + a_r) * 72 + k0 + a_k) * 2;
                const uint32_t boff = (uint32_t)((wc * 32 + b_r) * 72 + k0 + b_k) * 2;
                uint32_t ah[4], al[4];
                ldsm_x4(ah[0], ah[1], ah[2], ah[3], uPh + aoff);
                ldsm_x4(al[0], al[1], al[2], al[3], uPl + aoff);
                uint32_t bh[4][2], bl[4][2];
                #pragma unroll
                for (int nb = 0; nb < 2; nb++) {
                    ldsm_x4(bh[2*nb][0], bh[2*nb][1], bh[2*nb+1][0], bh[2*nb+1][1],
                            uVh + boff + nb * 16 * 72 * 2);
                    ldsm_x4(bl[2*nb][0], bl[2*nb][1], bl[2*nb+1][0], bl[2*nb+1][1],
                            uVl + boff + nb * 16 * 72 * 2);
                }
                #pragma unroll
                for (int nf = 0; nf < 4; nf++) {
                    mma16816(acc[hh][nf], ah, bh[nf]);
                    mma16816(acc[hh][nf], ah, bl[nf]);
                    mma16816(acc[hh][nf], al, bh[nf]);
                }
            }
        }
    }
    __syncthreads();

    // ---- epilogue: normalize, write ctx hi/lo ------------------------------
    const int qrow = lane >> 2;
    const int qcol = (lane & 3) << 1;
    #pragma unroll
    for (int hh = 0; hh < 2; hh++) {
        #pragma unroll
        for (int half = 0; half < 2; half++) {
            int r = wr * 16 + half * 8 + qrow;
            float inv = 1.0f / sSum[hh * 64 + r];
            long obase = ((long)b * N_SEQ + i0 + r) * DIM + (hg * 2 + hh) * HD;
            #pragma unroll
            for (int nf = 0; nf < 4; nf++) {
                int n = wc * 32 + nf * 8 + qcol;
                float ox = acc[hh][nf][half * 2 + 0] * inv;
                float oy = acc[hh][nf][half * 2 + 1] * inv;
                __nv_bfloat16 hx = __float2bfloat16(ox);
                __nv_bfloat16 hy = __float2bfloat16(oy);
                __nv_bfloat16 lx = __float2bfloat16(ox - __bfloat162float(hx));
                __nv_bfloat16 ly = __float2bfloat16(oy - __bfloat162float(hy));
                uint32_t uh = ((uint32_t)__bfloat16_as_ushort(hy) << 16)
                            | __bfloat16_as_ushort(hx);
                uint32_t ul = ((uint32_t)__bfloat16_as_ushort(ly) << 16)
                            | __bfloat16_as_ushort(lx);
                *(uint32_t*)&ctxh[obase + n] = uh;
                *(uint32_t*)&ctxl[obase + n] = ul;
            }
        }
    }
}

// ---------------------------------------------------------------------------
extern "C" void kernel_launch(void* const* d_in, const int* in_sizes, int n_in,
                              void* d_out, int out_size)
{
    const float* x      = (const float*)d_in[0];
    const float* W_qkv  = (const float*)d_in[1];
    const float* W_v    = (const float*)d_in[2];
    const float* W_proj = (const float*)d_in[3];
    const float* b_proj = (const float*)d_in[4];
    const float* mixl   = (const float*)d_in[5];
    float* out = (float*)d_out;

    float *pV, *pS4;
    __nv_bfloat16 *pxh, *pxl, *pWqh, *pWql, *pWvh, *pWvl, *pWph, *pWpl;
    __nv_bfloat16 *pYh, *pYl, *pch, *pcl, *pVth, *pVtl;
    cudaGetSymbolAddress((void**)&pV,   g_V);
    cudaGetSymbolAddress((void**)&pS4,  g_S4);
    cudaGetSymbolAddress((void**)&pxh,  g_xh);
    cudaGetSymbolAddress((void**)&pxl,  g_xl);
    cudaGetSymbolAddress((void**)&pWqh, g_Wqh);
    cudaGetSymbolAddress((void**)&pWql, g_Wql);
    cudaGetSymbolAddress((void**)&pWvh, g_Wvh);
    cudaGetSymbolAddress((void**)&pWvl, g_Wvl);
    cudaGetSymbolAddress((void**)&pWph, g_Wph);
    cudaGetSymbolAddress((void**)&pWpl, g_Wpl);
    cudaGetSymbolAddress((void**)&pYh,  g_Yh);
    cudaGetSymbolAddress((void**)&pYl,  g_Yl);
    cudaGetSymbolAddress((void**)&pch,  g_ch);
    cudaGetSymbolAddress((void**)&pcl,  g_cl);
    cudaGetSymbolAddress((void**)&pVth, g_Vth);
    cudaGetSymbolAddress((void**)&pVtl, g_Vtl);

    static bool attrDone = false;
    if (!attrDone) {
        cudaFuncSetAttribute(hmma_gemm_bf16,
                             cudaFuncAttributeMaxDynamicSharedMemorySize, GSMEM);
        cudaFuncSetAttribute(attn_kernel,
                             cudaFuncAttributeMaxDynamicSharedMemorySize, ATTN_SMEM);
        attrDone = true;
    }

    dim3 blk(256);
    const int NX = B_SZ * N_SEQ * DIM;   // 6291456
    const int NW = DIM * DIM;            // 589824

    // 0) split inputs to bf16 hi/lo
    split32<<<(NX / 4 + 255) / 256, blk>>>(x,      pxh, pxl, NX / 4);
    split32<<<(NW / 4 + 255) / 256, blk>>>(W_qkv, pWqh, pWql, NW / 4);
    split32<<<(NW / 4 + 255) / 256, blk>>>(W_v,   pWvh, pWvl, NW / 4);
    split32<<<(NW / 4 + 255) / 256, blk>>>(W_proj, pWph, pWpl, NW / 4);

    // 1) Y(h,l) = x @ W_qkv[0:512].T
    hmma_gemm_bf16<<<dim3(4, 64, 1), blk, GSMEM>>>(
        pxh, pxl, pWqh, pWql, nullptr, pYh, pYl, nullptr,
        DIM, DIM, DIM, 512, 1.0f, 0, 0, 0, 0, 0, 1);

    // 2) V = x @ W_v.T (f32)
    hmma_gemm_bf16<<<dim3(6, 64, 1), blk, GSMEM>>>(
        pxh, pxl, pWvh, pWvl, pV, nullptr, nullptr, nullptr,
        DIM, DIM, DIM, DIM, 1.0f, 0, 0, 0, 0, 0, 1);

    // 2b) V -> per-head transposed bf16 hi/lo
    vconvert<<<dim3(16, 96, 1), blk>>>(pV, pVth, pVtl);

    // 3) S4 = 0.125 * q @ k.T (f32)
    hmma_gemm_bf16<<<dim3(8, 8, B_SZ * KG), blk, GSMEM>>>(
        pYh, pYl, pYh + 256, pYl + 256, pS4, nullptr, nullptr, nullptr,
        HD, 512, 512, N_SEQ, 0.125f,
        (long)N_SEQ * 512, 64, (long)N_SEQ * 512, 64, (long)N_SEQ * N_SEQ, KG);

    // 4) attention (ctx hi/lo out)
    attn_kernel<<<dim3(16, 6, 8), blk, ATTN_SMEM>>>(pS4, pVth, pVtl, mixl, pch, pcl);

    // 5) out = ctx @ W_proj.T + b_proj
    hmma_gemm_bf16<<<dim3(6, 64, 1), blk, GSMEM>>>(
        pch, pcl, pWph, pWpl, out, nullptr, nullptr, b_proj,
        DIM, DIM, DIM, DIM, 1.0f, 0, 0, 0, 0, 0, 1);
}

// round 10
// speedup vs baseline: 1.1087x; 1.1087x over previous
#include <cuda_runtime.h>
#include <cuda_bf16.h>
#include <cuda_fp16.h>
#include <cstdint>

// ---------------------------------------------------------------------------
// FiSHAttention: B=8, N=1024, dim=p=768, HEAD_DIM=64, K_GLOBAL=4, H_eff=12
//   1) Y    = x @ Wqkv[0:512].T          (HMMA split-bf16 3-pass)
//   2) V    = x @ Wv.T                   (HMMA split-bf16)
//   2b) Vt  = transpose+fp16split of V   (per-head [d][j] hi/lo)
//   3) S4   = 0.125 * qg @ kg.T          (HMMA split-bf16, 32 batched)
//   4) attn: combine+exp2 (FMA) + PV on fp16 HMMA.
//      P fp16 (2^-11 rounding -> output ~4e-4, calibrated vs round-8 bf16
//      failure at 1.7e-3); V fp16 hi/lo -> 2-pass MMA (P Vh + P Vl).
//   5) out  = ctx @ Wproj.T + b_proj     (HMMA split-bf16)
// (Round 9 was an infra failure; this resubmits the same kernel.)
// ---------------------------------------------------------------------------

#define B_SZ   8
#define N_SEQ  1024
#define DIM    768
#define KG     4
#define HD     64
#define HEFF   12

__device__ float g_Y  [B_SZ * N_SEQ * 512];
__device__ float g_V  [B_SZ * N_SEQ * DIM];
__device__ float g_ctx[B_SZ * N_SEQ * DIM];
__device__ float g_S4 [(size_t)B_SZ * KG * N_SEQ * N_SEQ];
__device__ __half g_Vth[(size_t)B_SZ * HEFF * HD * N_SEQ];
__device__ __half g_Vtl[(size_t)B_SZ * HEFF * HD * N_SEQ];

// ------------------------------ helpers ------------------------------------
__device__ __forceinline__ uint32_t smem_u32(const void* p) {
    uint32_t a;
    asm("{ .reg .u64 t; cvta.to.shared.u64 t, %1; cvt.u32.u64 %0, t; }"
        : "=r"(a) : "l"(p));
    return a;
}
__device__ __forceinline__ void ldsm_x4(uint32_t& r0, uint32_t& r1,
                                        uint32_t& r2, uint32_t& r3, uint32_t addr) {
    asm volatile("ldmatrix.sync.aligned.m8n8.x4.shared.b16 {%0,%1,%2,%3}, [%4];"
        : "=r"(r0), "=r"(r1), "=r"(r2), "=r"(r3) : "r"(addr));
}
__device__ __forceinline__ void mma16816(float* c, const uint32_t* a,
                                         const uint32_t* b) {
    asm volatile("mma.sync.aligned.m16n8k16.row.col.f32.bf16.bf16.f32 "
        "{%0,%1,%2,%3}, {%4,%5,%6,%7}, {%8,%9}, {%0,%1,%2,%3};"
        : "+f"(c[0]), "+f"(c[1]), "+f"(c[2]), "+f"(c[3])
        : "r"(a[0]), "r"(a[1]), "r"(a[2]), "r"(a[3]), "r"(b[0]), "r"(b[1]));
}
__device__ __forceinline__ void mma16816h(float* c, const uint32_t* a,
                                          const uint32_t* b) {
    asm volatile("mma.sync.aligned.m16n8k16.row.col.f32.f16.f16.f32 "
        "{%0,%1,%2,%3}, {%4,%5,%6,%7}, {%8,%9}, {%0,%1,%2,%3};"
        : "+f"(c[0]), "+f"(c[1]), "+f"(c[2]), "+f"(c[3])
        : "r"(a[0]), "r"(a[1]), "r"(a[2]), "r"(a[3]), "r"(b[0]), "r"(b[1]));
}

__device__ __forceinline__ float fast_exp(float x) {
    x = fmaxf(x, -80.0f);
    const float L2E = 1.4426950408889634f;
    float t  = fmaf(x, L2E, 12582912.0f);
    float nf = t - 12582912.0f;
    int   ni = __float_as_int(t) - 0x4B400000;
    float f  = fmaf(x, L2E, -nf);
    f = fmaf(x, 1.9259629911266175e-8f, f);
    float p;
    p = 1.33335581e-3f;
    p = fmaf(p, f, 9.61812910e-3f);
    p = fmaf(p, f, 5.55041087e-2f);
    p = fmaf(p, f, 2.40226507e-1f);
    p = fmaf(p, f, 6.93147181e-1f);
    p = fmaf(p, f, 1.0f);
    return __int_as_float(__float_as_int(p) + (ni << 23));
}
__device__ __forceinline__ float fast_exp2(float y) {
    y = fmaxf(y, -100.0f);
    float t  = y + 12582912.0f;
    float nf = t - 12582912.0f;
    int   ni = __float_as_int(t) - 0x4B400000;
    float f  = y - nf;
    float p;
    p = 1.33335581e-3f;
    p = fmaf(p, f, 9.61812910e-3f);
    p = fmaf(p, f, 5.55041087e-2f);
    p = fmaf(p, f, 2.40226507e-1f);
    p = fmaf(p, f, 6.93147181e-1f);
    p = fmaf(p, f, 1.0f);
    return __int_as_float(__float_as_int(p) + (ni << 23));
}

// ===========================================================================
// HMMA split-bf16 TN GEMM (round-6 version; at mma.sync ceiling ~237 TF/s).
// ===========================================================================
#define BKC  32
#define TSTR 40

__global__ __launch_bounds__(256) void hmma_gemm(
    const float* __restrict__ A, const float* __restrict__ B,
    float* __restrict__ C, const float* __restrict__ bias,
    int K, int lda, int ldb, int ldc, float alpha,
    long sAo, long sAi, long sBo, long sBi, long sC, int innerMod)
{
    {
        int z = blockIdx.z;
        int outer = z / innerMod;
        int inner = z - outer * innerMod;
        A += (long)outer * sAo + (long)inner * sAi;
        B += (long)outer * sBo + (long)inner * sBi;
        C += (long)z * sC;
    }
    const int row0 = blockIdx.y * 128;
    const int col0 = blockIdx.x * 128;

    __shared__ __nv_bfloat16 sAh[128 * TSTR], sAl[128 * TSTR];
    __shared__ __nv_bfloat16 sBh[128 * TSTR], sBl[128 * TSTR];

    const int tid  = threadIdx.x;
    const int wid  = tid >> 5;
    const int lane = tid & 31;
    const int wm   = wid >> 1;
    const int wn   = wid & 1;

    const int a_r = lane & 15;
    const int a_k = (lane >> 4) << 3;
    const int b_r = (lane & 7) + ((lane >> 4) << 3);
    const int b_k = ((lane >> 3) & 1) << 3;

    const uint32_t uAh = smem_u32(sAh), uAl = smem_u32(sAl);
    const uint32_t uBh = smem_u32(sBh), uBl = smem_u32(sBl);

    float acc[2][8][4];
    #pragma unroll
    for (int i = 0; i < 2; i++)
        #pragma unroll
        for (int j = 0; j < 8; j++)
            #pragma unroll
            for (int q = 0; q < 4; q++) acc[i][j][q] = 0.0f;

    const int nch = K / BKC;
    for (int t = 0; t < nch; t++) {
        #pragma unroll
        for (int m = 0; m < 2; m++) {
            const float* src = m ? B : A;
            const int    ld  = m ? ldb : lda;
            const int    rb  = m ? col0 : row0;
            __nv_bfloat16* ph = m ? sBh : sAh;
            __nv_bfloat16* pl = m ? sBl : sAl;
            #pragma unroll
            for (int it = 0; it < 4; it++) {
                int e = it * 256 + tid;
                int r = e >> 3;
                int c = (e & 7) << 2;
                float4 v = *(const float4*)&src[(long)(rb + r) * ld + t * BKC + c];
                __nv_bfloat16 h0 = __float2bfloat16(v.x);
                __nv_bfloat16 h1 = __float2bfloat16(v.y);
                __nv_bfloat16 h2 = __float2bfloat16(v.z);
                __nv_bfloat16 h3 = __float2bfloat16(v.w);
                __nv_bfloat16 l0 = __float2bfloat16(v.x - __bfloat162float(h0));
                __nv_bfloat16 l1 = __float2bfloat16(v.y - __bfloat162float(h1));
                __nv_bfloat16 l2 = __float2bfloat16(v.z - __bfloat162float(h2));
                __nv_bfloat16 l3 = __float2bfloat16(v.w - __bfloat162float(h3));
                uint2 hv, lv;
                hv.x = ((uint32_t)__bfloat16_as_ushort(h1) << 16) | __bfloat16_as_ushort(h0);
                hv.y = ((uint32_t)__bfloat16_as_ushort(h3) << 16) | __bfloat16_as_ushort(h2);
                lv.x = ((uint32_t)__bfloat16_as_ushort(l1) << 16) | __bfloat16_as_ushort(l0);
                lv.y = ((uint32_t)__bfloat16_as_ushort(l3) << 16) | __bfloat16_as_ushort(l2);
                *(uint2*)&ph[r * TSTR + c] = hv;
                *(uint2*)&pl[r * TSTR + c] = lv;
            }
        }
        __syncthreads();

        #pragma unroll
        for (int ks = 0; ks < 2; ks++) {
            const int k0 = ks * 16;
            const uint32_t aoff = (uint32_t)((wm * 32 + a_r) * TSTR + k0 + a_k) * 2;
            const uint32_t boff = (uint32_t)((wn * 64 + b_r) * TSTR + k0 + b_k) * 2;

            uint32_t af[2][4];
            ldsm_x4(af[0][0], af[0][1], af[0][2], af[0][3], uAh + aoff);
            ldsm_x4(af[1][0], af[1][1], af[1][2], af[1][3], uAh + aoff + 16 * TSTR * 2);

            uint32_t bh[8][2], bl[8][2];
            #pragma unroll
            for (int nb = 0; nb < 4; nb++) {
                ldsm_x4(bh[2*nb][0], bh[2*nb][1], bh[2*nb+1][0], bh[2*nb+1][1],
                        uBh + boff + nb * 16 * TSTR * 2);
                ldsm_x4(bl[2*nb][0], bl[2*nb][1], bl[2*nb+1][0], bl[2*nb+1][1],
                        uBl + boff + nb * 16 * TSTR * 2);
            }
            #pragma unroll
            for (int mf = 0; mf < 2; mf++)
                #pragma unroll
                for (int nf = 0; nf < 8; nf++) {
                    mma16816(acc[mf][nf], af[mf], bh[nf]);
                    mma16816(acc[mf][nf], af[mf], bl[nf]);
                }
            ldsm_x4(af[0][0], af[0][1], af[0][2], af[0][3], uAl + aoff);
            ldsm_x4(af[1][0], af[1][1], af[1][2], af[1][3], uAl + aoff + 16 * TSTR * 2);
            #pragma unroll
            for (int mf = 0; mf < 2; mf++)
                #pragma unroll
                for (int nf = 0; nf < 8; nf++)
                    mma16816(acc[mf][nf], af[mf], bh[nf]);
        }
        __syncthreads();
    }

    const int qrow = lane >> 2;
    const int qcol = (lane & 3) << 1;
    #pragma unroll
    for (int mf = 0; mf < 2; mf++) {
        #pragma unroll
        for (int half = 0; half < 2; half++) {
            long r = row0 + wm * 32 + mf * 16 + half * 8 + qrow;
            #pragma unroll
            for (int nf = 0; nf < 8; nf++) {
                int n = col0 + wn * 64 + nf * 8 + qcol;
                float2 o;
                o.x = alpha * acc[mf][nf][half * 2 + 0];
                o.y = alpha * acc[mf][nf][half * 2 + 1];
                if (bias) { o.x += bias[n]; o.y += bias[n + 1]; }
                *(float2*)&C[r * ldc + n] = o;
            }
        }
    }
}

// ===========================================================================
// V transpose + fp16 hi/lo split.
// ===========================================================================
__global__ __launch_bounds__(256) void vconvert(
    const float* __restrict__ V, __half* __restrict__ Vth,
    __half* __restrict__ Vtl)
{
    const int j0   = blockIdx.x * 64;
    const int bhid = blockIdx.y;
    const int b    = bhid / HEFF;
    const int h    = bhid - b * HEFF;

    __shared__ float sT[64][68];
    const int tid = threadIdx.x;

    #pragma unroll
    for (int it = 0; it < 4; it++) {
        int e = it * 256 + tid;
        int j = e >> 4, dq = (e & 15) << 2;
        float4 v = *(const float4*)&V[((long)b * N_SEQ + j0 + j) * DIM + h * HD + dq];
        sT[dq + 0][j] = v.x; sT[dq + 1][j] = v.y;
        sT[dq + 2][j] = v.z; sT[dq + 3][j] = v.w;
    }
    __syncthreads();

    const int d = tid >> 2, jseg = (tid & 3) << 4;
    ushort hv[16], lv[16];
    #pragma unroll
    for (int t = 0; t < 16; t++) {
        float f = sT[d][jseg + t];
        __half hb = __float2half(f);
        __half lb = __float2half(f - __half2float(hb));
        hv[t] = __half_as_ushort(hb);
        lv[t] = __half_as_ushort(lb);
    }
    size_t dst = ((size_t)bhid * HD + d) * N_SEQ + j0 + jseg;
    *(uint4*)&Vth[dst]     = *(uint4*)&hv[0];
    *(uint4*)&Vth[dst + 8] = *(uint4*)&hv[8];
    *(uint4*)&Vtl[dst]     = *(uint4*)&lv[0];
    *(uint4*)&Vtl[dst + 8] = *(uint4*)&lv[8];
}

// ===========================================================================
// Attention v6: 2 heads/CTA, P fp16 (single), V fp16 hi/lo -> 2-pass MMA.
// Grid (16, 6, 8), 256 threads. smem ~56KB -> 2 CTA/SM.
// ===========================================================================
#define PBY 9216
#define OFF_V 0              // [Vh h0][Vh h1][Vl h0][Vl h1]
#define OFF_P (4 * PBY)      // [P h0][P h1]
#define OFF_SUM (6 * PBY)
#define OFF_MIX (OFF_SUM + 512)
#define ATTN_SMEM (OFF_MIX + 64)

__global__ __launch_bounds__(256, 2) void attn_kernel(
    const float* __restrict__ S4,
    const __half* __restrict__ Vth, const __half* __restrict__ Vtl,
    const float* __restrict__ mixl, float* __restrict__ ctx)
{
    const int ib = blockIdx.x;
    const int hg = blockIdx.y;
    const int b  = blockIdx.z;

    extern __shared__ char sm[];
    const uint32_t sb = smem_u32(sm);
    float* sSum = (float*)(sm + OFF_SUM);
    float* sMix = (float*)(sm + OFF_MIX);

    const int tid  = threadIdx.x;
    const int wid  = tid >> 5;
    const int lane = tid & 31;
    const int wr   = wid >> 1;
    const int wc   = wid & 1;
    const int a_r  = lane & 15;
    const int a_k  = (lane >> 4) << 3;
    const int b_r  = (lane & 7) + ((lane >> 4) << 3);
    const int b_k  = ((lane >> 3) & 1) << 3;

    if (tid < 128) sSum[tid] = 0.0f;
    if (tid < 8) {
        int hh = tid >> 2, k = tid & 3;
        const float* ml = mixl + (hg * 2 + hh) * 4;
        float l0 = ml[0], l1 = ml[1], l2 = ml[2], l3 = ml[3];
        float m  = fmaxf(fmaxf(l0, l1), fmaxf(l2, l3));
        float e0 = fast_exp(l0 - m), e1 = fast_exp(l1 - m);
        float e2 = fast_exp(l2 - m), e3 = fast_exp(l3 - m);
        float s  = e0 + e1 + e2 + e3;
        float mine = (k == 0) ? e0 : (k == 1) ? e1 : (k == 2) ? e2 : e3;
        sMix[hh * 4 + k] = (mine / s) * 1.4426950408889634f;
    }

    const int i0   = ib * 64;
    const int arow = tid >> 2;
    const int aq   = tid & 3;
    const float* S4b = S4 + (long)b * KG * N_SEQ * N_SEQ;
    const long   PL  = (long)N_SEQ * N_SEQ;
    const size_t vbase0 = ((size_t)(b * HEFF + hg * 2 + 0)) * HD * N_SEQ;
    const size_t vbase1 = ((size_t)(b * HEFF + hg * 2 + 1)) * HD * N_SEQ;

    float acc[2][4][4];
    #pragma unroll
    for (int i = 0; i < 2; i++)
        #pragma unroll
        for (int j = 0; j < 4; j++)
            #pragma unroll
            for (int q = 0; q < 4; q++) acc[i][j][q] = 0.0f;

    for (int j0 = 0; j0 < N_SEQ; j0 += 64) {
        __syncthreads();   // prev MMAs done before overwriting V/P

        // ---- load V fp16 tiles (4 buffers x 512 uint4) ---------------------
        #pragma unroll
        for (int it = 0; it < 8; it++) {
            int idx = it * 256 + tid;
            int bufid = idx >> 9;
            int r = (idx >> 3) & 63;
            int q = idx & 7;
            const __half* src = (bufid & 2) ? Vtl : Vth;
            size_t so = ((bufid & 1) ? vbase1 : vbase0) + (size_t)r * N_SEQ + j0 + q * 8;
            *(uint4*)(sm + OFF_V + bufid * PBY + (r * 72 + q * 8) * 2) =
                *(const uint4*)&src[so];
        }

        // ---- phase A: combine + exp2, store P as fp16 ----------------------
        {
            const float mx00 = sMix[0], mx01 = sMix[1], mx02 = sMix[2], mx03 = sMix[3];
            const float mx10 = sMix[4], mx11 = sMix[5], mx12 = sMix[6], mx13 = sMix[7];
            const float* base = S4b + (long)(i0 + arow) * N_SEQ + j0 + aq * 16;
            float s0 = 0.0f, s1 = 0.0f;
            #pragma unroll
            for (int c = 0; c < 4; c++) {
                float4 a  = *(const float4*)(base + c * 4);
                float4 p1 = *(const float4*)(base + PL + c * 4);
                float4 p2 = *(const float4*)(base + 2 * PL + c * 4);
                float4 p3 = *(const float4*)(base + 3 * PL + c * 4);
                const uint32_t po = (uint32_t)(arow * 72 + aq * 16 + c * 4) * 2;
                #pragma unroll
                for (int hh = 0; hh < 2; hh++) {
                    float m0 = hh ? mx10 : mx00, m1 = hh ? mx11 : mx01;
                    float m2 = hh ? mx12 : mx02, m3 = hh ? mx13 : mx03;
                    float q0 = fast_exp2(fmaf(m3, p3.x, fmaf(m2, p2.x, fmaf(m1, p1.x, m0 * a.x))));
                    float q1 = fast_exp2(fmaf(m3, p3.y, fmaf(m2, p2.y, fmaf(m1, p1.y, m0 * a.y))));
                    float q2 = fast_exp2(fmaf(m3, p3.z, fmaf(m2, p2.z, fmaf(m1, p1.z, m0 * a.z))));
                    float q3 = fast_exp2(fmaf(m3, p3.w, fmaf(m2, p2.w, fmaf(m1, p1.w, m0 * a.w))));
                    if (hh) s1 += (q0 + q1) + (q2 + q3);
                    else    s0 += (q0 + q1) + (q2 + q3);
                    __half h0 = __float2half(q0);
                    __half h1 = __float2half(q1);
                    __half h2 = __float2half(q2);
                    __half h3 = __float2half(q3);
                    uint2 hv;
                    hv.x = ((uint32_t)__half_as_ushort(h1) << 16) | __half_as_ushort(h0);
                    hv.y = ((uint32_t)__half_as_ushort(h3) << 16) | __half_as_ushort(h2);
                    *(uint2*)(sm + OFF_P + hh * PBY + po) = hv;
                }
            }
            s0 += __shfl_xor_sync(0xffffffffu, s0, 1);
            s0 += __shfl_xor_sync(0xffffffffu, s0, 2);
            s1 += __shfl_xor_sync(0xffffffffu, s1, 1);
            s1 += __shfl_xor_sync(0xffffffffu, s1, 2);
            if (aq == 0) {
                sSum[arow]      += s0;
                sSum[64 + arow] += s1;
            }
        }
        __syncthreads();

        // ---- MMA: both heads, 2-pass fp16 (P Vh + P Vl) --------------------
        #pragma unroll
        for (int hh = 0; hh < 2; hh++) {
            const uint32_t uP  = sb + OFF_P + hh * PBY;
            const uint32_t uVh = sb + OFF_V + hh * PBY;
            const uint32_t uVl = uVh + 2 * PBY;
            #pragma unroll
            for (int ks = 0; ks < 4; ks++) {
                const int k0 = ks * 16;
                const uint32_t aoff = (uint32_t)((wr * 16 + a_r) * 72 + k0 + a_k) * 2;
                const uint32_t boff = (uint32_t)((wc * 32 + b_r) * 72 + k0 + b_k) * 2;
                uint32_t ah[4];
                ldsm_x4(ah[0], ah[1], ah[2], ah[3], uP + aoff);
                uint32_t bh[4][2], bl[4][2];
                #pragma unroll
                for (int nb = 0; nb < 2; nb++) {
                    ldsm_x4(bh[2*nb][0], bh[2*nb][1], bh[2*nb+1][0], bh[2*nb+1][1],
                            uVh + boff + nb * 16 * 72 * 2);
                    ldsm_x4(bl[2*nb][0], bl[2*nb][1], bl[2*nb+1][0], bl[2*nb+1][1],
                            uVl + boff + nb * 16 * 72 * 2);
                }
                #pragma unroll
                for (int nf = 0; nf < 4; nf++) {
                    mma16816h(acc[hh][nf], ah, bh[nf]);
                    mma16816h(acc[hh][nf], ah, bl[nf]);
                }
            }
        }
    }
    __syncthreads();

    // ---- epilogue: normalize, write ctx ------------------------------------
    const int qrow = lane >> 2;
    const int qcol = (lane & 3) << 1;
    #pragma unroll
    for (int hh = 0; hh < 2; hh++) {
        #pragma unroll
        for (int half = 0; half < 2; half++) {
            int r = wr * 16 + half * 8 + qrow;
            float inv = 1.0f / sSum[hh * 64 + r];
            long obase = ((long)b * N_SEQ + i0 + r) * DIM + (hg * 2 + hh) * HD;
            #pragma unroll
            for (int nf = 0; nf < 4; nf++) {
                int n = wc * 32 + nf * 8 + qcol;
                float2 o;
                o.x = acc[hh][nf][half * 2 + 0] * inv;
                o.y = acc[hh][nf][half * 2 + 1] * inv;
                *(float2*)&ctx[obase + n] = o;
            }
        }
    }
}

// ---------------------------------------------------------------------------
extern "C" void kernel_launch(void* const* d_in, const int* in_sizes, int n_in,
                              void* d_out, int out_size)
{
    const float* x      = (const float*)d_in[0];
    const float* W_qkv  = (const float*)d_in[1];
    const float* W_v    = (const float*)d_in[2];
    const float* W_proj = (const float*)d_in[3];
    const float* b_proj = (const float*)d_in[4];
    const float* mixl   = (const float*)d_in[5];
    float* out = (float*)d_out;

    float *pY, *pV, *pCtx, *pS4;
    __half *pVth, *pVtl;
    cudaGetSymbolAddress((void**)&pY,   g_Y);
    cudaGetSymbolAddress((void**)&pV,   g_V);
    cudaGetSymbolAddress((void**)&pCtx, g_ctx);
    cudaGetSymbolAddress((void**)&pS4,  g_S4);
    cudaGetSymbolAddress((void**)&pVth, g_Vth);
    cudaGetSymbolAddress((void**)&pVtl, g_Vtl);

    static bool attrDone = false;
    if (!attrDone) {
        cudaFuncSetAttribute(attn_kernel,
                             cudaFuncAttributeMaxDynamicSharedMemorySize, ATTN_SMEM);
        attrDone = true;
    }

    dim3 blk(256);

    // 1) Y = x @ W_qkv[0:512].T
    hmma_gemm<<<dim3(4, 64, 1), blk>>>(
        x, W_qkv, pY, nullptr, DIM, DIM, DIM, 512, 1.0f, 0, 0, 0, 0, 0, 1);

    // 2) V = x @ W_v.T
    hmma_gemm<<<dim3(6, 64, 1), blk>>>(
        x, W_v, pV, nullptr, DIM, DIM, DIM, DIM, 1.0f, 0, 0, 0, 0, 0, 1);

    // 2b) V -> per-head transposed fp16 hi/lo
    vconvert<<<dim3(16, 96, 1), blk>>>(pV, pVth, pVtl);

    // 3) S4 = 0.125 * q @ k.T
    hmma_gemm<<<dim3(8, 8, B_SZ * KG), blk>>>(
        pY, pY + 256, pS4, nullptr, HD, 512, 512, N_SEQ, 0.125f,
        (long)N_SEQ * 512, 64, (long)N_SEQ * 512, 64, (long)N_SEQ * N_SEQ, KG);

    // 4) attention
    attn_kernel<<<dim3(16, 6, 8), blk, ATTN_SMEM>>>(pS4, pVth, pVtl, mixl, pCtx);

    // 5) out = ctx @ W_proj.T + b_proj
    hmma_gemm<<<dim3(6, 64, 1), blk>>>(
        pCtx, W_proj, out, b_proj, DIM, DIM, DIM, DIM, 1.0f, 0, 0, 0, 0, 0, 1);
}

// round 11
// speedup vs baseline: 1.3796x; 1.2444x over previous
#include <cuda_runtime.h>
#include <cuda_bf16.h>
#include <cuda_fp16.h>
#include <cstdint>

// ---------------------------------------------------------------------------
// FiSHAttention: B=8, N=1024, dim=p=768, HEAD_DIM=64, K_GLOBAL=4, H_eff=12
//   1) Y    = x @ Wqkv[0:512].T          (HMMA fp16 2-pass: A f16, B hi/lo)
//   2) V    = x @ Wv.T                   (HMMA fp16 2-pass)
//   2b) Vt  = transpose+fp16 of V        (per-head [d][j], single precision)
//   3) S4   = 0.125 * qg @ kg.T          (HMMA fp16 2-pass, 32 batched)
//   4) attn: combine+exp2 (FMA) + PV 1-pass fp16 HMMA (P f16 x V f16)
//   5) out  = ctx @ Wproj.T + b_proj     (HMMA fp16 2-pass)
// Error budget (calibrated: out_rel_err ~= 0.44 * operand unit rounding):
//   each fp16-single operand ~2.2e-4; quadrature total ~4.5e-4 < 1e-3.
// ---------------------------------------------------------------------------

#define B_SZ   8
#define N_SEQ  1024
#define DIM    768
#define KG     4
#define HD     64
#define HEFF   12

__device__ float g_Y  [B_SZ * N_SEQ * 512];
__device__ float g_V  [B_SZ * N_SEQ * DIM];
__device__ float g_ctx[B_SZ * N_SEQ * DIM];
__device__ float g_S4 [(size_t)B_SZ * KG * N_SEQ * N_SEQ];
__device__ __half g_Vt[(size_t)B_SZ * HEFF * HD * N_SEQ];

// ------------------------------ helpers ------------------------------------
__device__ __forceinline__ uint32_t smem_u32(const void* p) {
    uint32_t a;
    asm("{ .reg .u64 t; cvta.to.shared.u64 t, %1; cvt.u32.u64 %0, t; }"
        : "=r"(a) : "l"(p));
    return a;
}
__device__ __forceinline__ void ldsm_x4(uint32_t& r0, uint32_t& r1,
                                        uint32_t& r2, uint32_t& r3, uint32_t addr) {
    asm volatile("ldmatrix.sync.aligned.m8n8.x4.shared.b16 {%0,%1,%2,%3}, [%4];"
        : "=r"(r0), "=r"(r1), "=r"(r2), "=r"(r3) : "r"(addr));
}
__device__ __forceinline__ void mma16816h(float* c, const uint32_t* a,
                                          const uint32_t* b) {
    asm volatile("mma.sync.aligned.m16n8k16.row.col.f32.f16.f16.f32 "
        "{%0,%1,%2,%3}, {%4,%5,%6,%7}, {%8,%9}, {%0,%1,%2,%3};"
        : "+f"(c[0]), "+f"(c[1]), "+f"(c[2]), "+f"(c[3])
        : "r"(a[0]), "r"(a[1]), "r"(a[2]), "r"(a[3]), "r"(b[0]), "r"(b[1]));
}

__device__ __forceinline__ float fast_exp(float x) {
    x = fmaxf(x, -80.0f);
    const float L2E = 1.4426950408889634f;
    float t  = fmaf(x, L2E, 12582912.0f);
    float nf = t - 12582912.0f;
    int   ni = __float_as_int(t) - 0x4B400000;
    float f  = fmaf(x, L2E, -nf);
    f = fmaf(x, 1.9259629911266175e-8f, f);
    float p;
    p = 1.33335581e-3f;
    p = fmaf(p, f, 9.61812910e-3f);
    p = fmaf(p, f, 5.55041087e-2f);
    p = fmaf(p, f, 2.40226507e-1f);
    p = fmaf(p, f, 6.93147181e-1f);
    p = fmaf(p, f, 1.0f);
    return __int_as_float(__float_as_int(p) + (ni << 23));
}
__device__ __forceinline__ float fast_exp2(float y) {
    y = fmaxf(y, -100.0f);
    float t  = y + 12582912.0f;
    float nf = t - 12582912.0f;
    int   ni = __float_as_int(t) - 0x4B400000;
    float f  = y - nf;
    float p;
    p = 1.33335581e-3f;
    p = fmaf(p, f, 9.61812910e-3f);
    p = fmaf(p, f, 5.55041087e-2f);
    p = fmaf(p, f, 2.40226507e-1f);
    p = fmaf(p, f, 6.93147181e-1f);
    p = fmaf(p, f, 1.0f);
    return __int_as_float(__float_as_int(p) + (ni << 23));
}

// ===========================================================================
// HMMA fp16 2-pass TN GEMM: C = alpha * A @ B^T (+bias).
// A single fp16 (2.2e-4 contribution), B split hi/lo fp16 (negligible).
// CTA 128x128, 8 warps (4x2), warp tile 32x64, BK=32. smem ~30KB.
// ===========================================================================
#define BKC  32
#define TSTR 40

__global__ __launch_bounds__(256) void hmma_gemm(
    const float* __restrict__ A, const float* __restrict__ B,
    float* __restrict__ C, const float* __restrict__ bias,
    int K, int lda, int ldb, int ldc, float alpha,
    long sAo, long sAi, long sBo, long sBi, long sC, int innerMod)
{
    {
        int z = blockIdx.z;
        int outer = z / innerMod;
        int inner = z - outer * innerMod;
        A += (long)outer * sAo + (long)inner * sAi;
        B += (long)outer * sBo + (long)inner * sBi;
        C += (long)z * sC;
    }
    const int row0 = blockIdx.y * 128;
    const int col0 = blockIdx.x * 128;

    __shared__ __half sA [128 * TSTR];
    __shared__ __half sBh[128 * TSTR], sBl[128 * TSTR];

    const int tid  = threadIdx.x;
    const int wid  = tid >> 5;
    const int lane = tid & 31;
    const int wm   = wid >> 1;
    const int wn   = wid & 1;

    const int a_r = lane & 15;
    const int a_k = (lane >> 4) << 3;
    const int b_r = (lane & 7) + ((lane >> 4) << 3);
    const int b_k = ((lane >> 3) & 1) << 3;

    const uint32_t uA  = smem_u32(sA);
    const uint32_t uBh = smem_u32(sBh), uBl = smem_u32(sBl);

    float acc[2][8][4];
    #pragma unroll
    for (int i = 0; i < 2; i++)
        #pragma unroll
        for (int j = 0; j < 8; j++)
            #pragma unroll
            for (int q = 0; q < 4; q++) acc[i][j][q] = 0.0f;

    const int nch = K / BKC;
    for (int t = 0; t < nch; t++) {
        // ---- A: single fp16 -------------------------------------------------
        #pragma unroll
        for (int it = 0; it < 4; it++) {
            int e = it * 256 + tid;
            int r = e >> 3;
            int c = (e & 7) << 2;
            float4 v = *(const float4*)&A[(long)(row0 + r) * lda + t * BKC + c];
            __half h0 = __float2half(v.x), h1 = __float2half(v.y);
            __half h2 = __float2half(v.z), h3 = __float2half(v.w);
            uint2 hv;
            hv.x = ((uint32_t)__half_as_ushort(h1) << 16) | __half_as_ushort(h0);
            hv.y = ((uint32_t)__half_as_ushort(h3) << 16) | __half_as_ushort(h2);
            *(uint2*)&sA[r * TSTR + c] = hv;
        }
        // ---- B: hi/lo fp16 --------------------------------------------------
        #pragma unroll
        for (int it = 0; it < 4; it++) {
            int e = it * 256 + tid;
            int r = e >> 3;
            int c = (e & 7) << 2;
            float4 v = *(const float4*)&B[(long)(col0 + r) * ldb + t * BKC + c];
            __half h0 = __float2half(v.x), h1 = __float2half(v.y);
            __half h2 = __float2half(v.z), h3 = __float2half(v.w);
            __half l0 = __float2half(v.x - __half2float(h0));
            __half l1 = __float2half(v.y - __half2float(h1));
            __half l2 = __float2half(v.z - __half2float(h2));
            __half l3 = __float2half(v.w - __half2float(h3));
            uint2 hv, lv;
            hv.x = ((uint32_t)__half_as_ushort(h1) << 16) | __half_as_ushort(h0);
            hv.y = ((uint32_t)__half_as_ushort(h3) << 16) | __half_as_ushort(h2);
            lv.x = ((uint32_t)__half_as_ushort(l1) << 16) | __half_as_ushort(l0);
            lv.y = ((uint32_t)__half_as_ushort(l3) << 16) | __half_as_ushort(l2);
            *(uint2*)&sBh[r * TSTR + c] = hv;
            *(uint2*)&sBl[r * TSTR + c] = lv;
        }
        __syncthreads();

        #pragma unroll
        for (int ks = 0; ks < 2; ks++) {
            const int k0 = ks * 16;
            const uint32_t aoff = (uint32_t)((wm * 32 + a_r) * TSTR + k0 + a_k) * 2;
            const uint32_t boff = (uint32_t)((wn * 64 + b_r) * TSTR + k0 + b_k) * 2;

            uint32_t af[2][4];
            ldsm_x4(af[0][0], af[0][1], af[0][2], af[0][3], uA + aoff);
            ldsm_x4(af[1][0], af[1][1], af[1][2], af[1][3], uA + aoff + 16 * TSTR * 2);

            uint32_t bh[8][2], bl[8][2];
            #pragma unroll
            for (int nb = 0; nb < 4; nb++) {
                ldsm_x4(bh[2*nb][0], bh[2*nb][1], bh[2*nb+1][0], bh[2*nb+1][1],
                        uBh + boff + nb * 16 * TSTR * 2);
                ldsm_x4(bl[2*nb][0], bl[2*nb][1], bl[2*nb+1][0], bl[2*nb+1][1],
                        uBl + boff + nb * 16 * TSTR * 2);
            }
            #pragma unroll
            for (int mf = 0; mf < 2; mf++)
                #pragma unroll
                for (int nf = 0; nf < 8; nf++) {
                    mma16816h(acc[mf][nf], af[mf], bh[nf]);
                    mma16816h(acc[mf][nf], af[mf], bl[nf]);
                }
        }
        __syncthreads();
    }

    const int qrow = lane >> 2;
    const int qcol = (lane & 3) << 1;
    #pragma unroll
    for (int mf = 0; mf < 2; mf++) {
        #pragma unroll
        for (int half = 0; half < 2; half++) {
            long r = row0 + wm * 32 + mf * 16 + half * 8 + qrow;
            #pragma unroll
            for (int nf = 0; nf < 8; nf++) {
                int n = col0 + wn * 64 + nf * 8 + qcol;
                float2 o;
                o.x = alpha * acc[mf][nf][half * 2 + 0];
                o.y = alpha * acc[mf][nf][half * 2 + 1];
                if (bias) { o.x += bias[n]; o.y += bias[n + 1]; }
                *(float2*)&C[r * ldc + n] = o;
            }
        }
    }
}

// ===========================================================================
// V transpose + fp16 convert (single precision).
// ===========================================================================
__global__ __launch_bounds__(256) void vconvert(
    const float* __restrict__ V, __half* __restrict__ Vt)
{
    const int j0   = blockIdx.x * 64;
    const int bhid = blockIdx.y;
    const int b    = bhid / HEFF;
    const int h    = bhid - b * HEFF;

    __shared__ float sT[64][68];
    const int tid = threadIdx.x;

    #pragma unroll
    for (int it = 0; it < 4; it++) {
        int e = it * 256 + tid;
        int j = e >> 4, dq = (e & 15) << 2;
        float4 v = *(const float4*)&V[((long)b * N_SEQ + j0 + j) * DIM + h * HD + dq];
        sT[dq + 0][j] = v.x; sT[dq + 1][j] = v.y;
        sT[dq + 2][j] = v.z; sT[dq + 3][j] = v.w;
    }
    __syncthreads();

    const int d = tid >> 2, jseg = (tid & 3) << 4;
    ushort hv[16];
    #pragma unroll
    for (int t = 0; t < 16; t++)
        hv[t] = __half_as_ushort(__float2half(sT[d][jseg + t]));
    size_t dst = ((size_t)bhid * HD + d) * N_SEQ + j0 + jseg;
    *(uint4*)&Vt[dst]     = *(uint4*)&hv[0];
    *(uint4*)&Vt[dst + 8] = *(uint4*)&hv[8];
}

// ===========================================================================
// Attention v7: 2 heads/CTA, P fp16, V fp16 -> 1-pass MMA.
// Grid (16, 6, 8), 256 threads. smem ~37.4KB -> 2+ CTA/SM.
// ===========================================================================
#define PBY 9216
#define OFF_V 0              // [V h0][V h1]
#define OFF_P (2 * PBY)      // [P h0][P h1]
#define OFF_SUM (4 * PBY)
#define OFF_MIX (OFF_SUM + 512)
#define ATTN_SMEM (OFF_MIX + 64)

__global__ __launch_bounds__(256, 2) void attn_kernel(
    const float* __restrict__ S4, const __half* __restrict__ Vt,
    const float* __restrict__ mixl, float* __restrict__ ctx)
{
    const int ib = blockIdx.x;
    const int hg = blockIdx.y;
    const int b  = blockIdx.z;

    extern __shared__ char sm[];
    const uint32_t sb = smem_u32(sm);
    float* sSum = (float*)(sm + OFF_SUM);
    float* sMix = (float*)(sm + OFF_MIX);

    const int tid  = threadIdx.x;
    const int wid  = tid >> 5;
    const int lane = tid & 31;
    const int wr   = wid >> 1;
    const int wc   = wid & 1;
    const int a_r  = lane & 15;
    const int a_k  = (lane >> 4) << 3;
    const int b_r  = (lane & 7) + ((lane >> 4) << 3);
    const int b_k  = ((lane >> 3) & 1) << 3;

    if (tid < 128) sSum[tid] = 0.0f;
    if (tid < 8) {
        int hh = tid >> 2, k = tid & 3;
        const float* ml = mixl + (hg * 2 + hh) * 4;
        float l0 = ml[0], l1 = ml[1], l2 = ml[2], l3 = ml[3];
        float m  = fmaxf(fmaxf(l0, l1), fmaxf(l2, l3));
        float e0 = fast_exp(l0 - m), e1 = fast_exp(l1 - m);
        float e2 = fast_exp(l2 - m), e3 = fast_exp(l3 - m);
        float s  = e0 + e1 + e2 + e3;
        float mine = (k == 0) ? e0 : (k == 1) ? e1 : (k == 2) ? e2 : e3;
        sMix[hh * 4 + k] = (mine / s) * 1.4426950408889634f;
    }

    const int i0   = ib * 64;
    const int arow = tid >> 2;
    const int aq   = tid & 3;
    const float* S4b = S4 + (long)b * KG * N_SEQ * N_SEQ;
    const long   PL  = (long)N_SEQ * N_SEQ;
    const size_t vbase0 = ((size_t)(b * HEFF + hg * 2 + 0)) * HD * N_SEQ;
    const size_t vbase1 = ((size_t)(b * HEFF + hg * 2 + 1)) * HD * N_SEQ;

    float acc[2][4][4];
    #pragma unroll
    for (int i = 0; i < 2; i++)
        #pragma unroll
        for (int j = 0; j < 4; j++)
            #pragma unroll
            for (int q = 0; q < 4; q++) acc[i][j][q] = 0.0f;

    for (int j0 = 0; j0 < N_SEQ; j0 += 64) {
        __syncthreads();   // prev MMAs done before overwriting V/P

        // ---- load V fp16 tiles (2 buffers x 512 uint4) ---------------------
        #pragma unroll
        for (int it = 0; it < 4; it++) {
            int idx = it * 256 + tid;
            int bufid = idx >> 9;          // 0: head0, 1: head1
            int r = (idx >> 3) & 63;
            int q = idx & 7;
            size_t so = (bufid ? vbase1 : vbase0) + (size_t)r * N_SEQ + j0 + q * 8;
            *(uint4*)(sm + OFF_V + bufid * PBY + (r * 72 + q * 8) * 2) =
                *(const uint4*)&Vt[so];
        }

        // ---- phase A: combine + exp2, store P as fp16 ----------------------
        {
            const float mx00 = sMix[0], mx01 = sMix[1], mx02 = sMix[2], mx03 = sMix[3];
            const float mx10 = sMix[4], mx11 = sMix[5], mx12 = sMix[6], mx13 = sMix[7];
            const float* base = S4b + (long)(i0 + arow) * N_SEQ + j0 + aq * 16;
            float s0 = 0.0f, s1 = 0.0f;
            #pragma unroll
            for (int c = 0; c < 4; c++) {
                float4 a  = *(const float4*)(base + c * 4);
                float4 p1 = *(const float4*)(base + PL + c * 4);
                float4 p2 = *(const float4*)(base + 2 * PL + c * 4);
                float4 p3 = *(const float4*)(base + 3 * PL + c * 4);
                const uint32_t po = (uint32_t)(arow * 72 + aq * 16 + c * 4) * 2;
                #pragma unroll
                for (int hh = 0; hh < 2; hh++) {
                    float m0 = hh ? mx10 : mx00, m1 = hh ? mx11 : mx01;
                    float m2 = hh ? mx12 : mx02, m3 = hh ? mx13 : mx03;
                    float q0 = fast_exp2(fmaf(m3, p3.x, fmaf(m2, p2.x, fmaf(m1, p1.x, m0 * a.x))));
                    float q1 = fast_exp2(fmaf(m3, p3.y, fmaf(m2, p2.y, fmaf(m1, p1.y, m0 * a.y))));
                    float q2 = fast_exp2(fmaf(m3, p3.z, fmaf(m2, p2.z, fmaf(m1, p1.z, m0 * a.z))));
                    float q3 = fast_exp2(fmaf(m3, p3.w, fmaf(m2, p2.w, fmaf(m1, p1.w, m0 * a.w))));
                    if (hh) s1 += (q0 + q1) + (q2 + q3);
                    else    s0 += (q0 + q1) + (q2 + q3);
                    __half h0 = __float2half(q0);
                    __half h1 = __float2half(q1);
                    __half h2 = __float2half(q2);
                    __half h3 = __float2half(q3);
                    uint2 hv;
                    hv.x = ((uint32_t)__half_as_ushort(h1) << 16) | __half_as_ushort(h0);
                    hv.y = ((uint32_t)__half_as_ushort(h3) << 16) | __half_as_ushort(h2);
                    *(uint2*)(sm + OFF_P + hh * PBY + po) = hv;
                }
            }
            s0 += __shfl_xor_sync(0xffffffffu, s0, 1);
            s0 += __shfl_xor_sync(0xffffffffu, s0, 2);
            s1 += __shfl_xor_sync(0xffffffffu, s1, 1);
            s1 += __shfl_xor_sync(0xffffffffu, s1, 2);
            if (aq == 0) {
                sSum[arow]      += s0;
                sSum[64 + arow] += s1;
            }
        }
        __syncthreads();

        // ---- MMA: both heads, 1-pass fp16 (P @ V) --------------------------
        #pragma unroll
        for (int hh = 0; hh < 2; hh++) {
            const uint32_t uP = sb + OFF_P + hh * PBY;
            const uint32_t uV = sb + OFF_V + hh * PBY;
            #pragma unroll
            for (int ks = 0; ks < 4; ks++) {
                const int k0 = ks * 16;
                const uint32_t aoff = (uint32_t)((wr * 16 + a_r) * 72 + k0 + a_k) * 2;
                const uint32_t boff = (uint32_t)((wc * 32 + b_r) * 72 + k0 + b_k) * 2;
                uint32_t ah[4];
                ldsm_x4(ah[0], ah[1], ah[2], ah[3], uP + aoff);
                uint32_t bv[4][2];
                #pragma unroll
                for (int nb = 0; nb < 2; nb++)
                    ldsm_x4(bv[2*nb][0], bv[2*nb][1], bv[2*nb+1][0], bv[2*nb+1][1],
                            uV + boff + nb * 16 * 72 * 2);
                #pragma unroll
                for (int nf = 0; nf < 4; nf++)
                    mma16816h(acc[hh][nf], ah, bv[nf]);
            }
        }
    }
    __syncthreads();

    // ---- epilogue: normalize, write ctx ------------------------------------
    const int qrow = lane >> 2;
    const int qcol = (lane & 3) << 1;
    #pragma unroll
    for (int hh = 0; hh < 2; hh++) {
        #pragma unroll
        for (int half = 0; half < 2; half++) {
            int r = wr * 16 + half * 8 + qrow;
            float inv = 1.0f / sSum[hh * 64 + r];
            long obase = ((long)b * N_SEQ + i0 + r) * DIM + (hg * 2 + hh) * HD;
            #pragma unroll
            for (int nf = 0; nf < 4; nf++) {
                int n = wc * 32 + nf * 8 + qcol;
                float2 o;
                o.x = acc[hh][nf][half * 2 + 0] * inv;
                o.y = acc[hh][nf][half * 2 + 1] * inv;
                *(float2*)&ctx[obase + n] = o;
            }
        }
    }
}

// ---------------------------------------------------------------------------
extern "C" void kernel_launch(void* const* d_in, const int* in_sizes, int n_in,
                              void* d_out, int out_size)
{
    const float* x      = (const float*)d_in[0];
    const float* W_qkv  = (const float*)d_in[1];
    const float* W_v    = (const float*)d_in[2];
    const float* W_proj = (const float*)d_in[3];
    const float* b_proj = (const float*)d_in[4];
    const float* mixl   = (const float*)d_in[5];
    float* out = (float*)d_out;

    float *pY, *pV, *pCtx, *pS4;
    __half *pVt;
    cudaGetSymbolAddress((void**)&pY,   g_Y);
    cudaGetSymbolAddress((void**)&pV,   g_V);
    cudaGetSymbolAddress((void**)&pCtx, g_ctx);
    cudaGetSymbolAddress((void**)&pS4,  g_S4);
    cudaGetSymbolAddress((void**)&pVt,  g_Vt);

    static bool attrDone = false;
    if (!attrDone) {
        cudaFuncSetAttribute(attn_kernel,
                             cudaFuncAttributeMaxDynamicSharedMemorySize, ATTN_SMEM);
        attrDone = true;
    }

    dim3 blk(256);

    // 1) Y = x @ W_qkv[0:512].T
    hmma_gemm<<<dim3(4, 64, 1), blk>>>(
        x, W_qkv, pY, nullptr, DIM, DIM, DIM, 512, 1.0f, 0, 0, 0, 0, 0, 1);

    // 2) V = x @ W_v.T
    hmma_gemm<<<dim3(6, 64, 1), blk>>>(
        x, W_v, pV, nullptr, DIM, DIM, DIM, DIM, 1.0f, 0, 0, 0, 0, 0, 1);

    // 2b) V -> per-head transposed fp16
    vconvert<<<dim3(16, 96, 1), blk>>>(pV, pVt);

    // 3) S4 = 0.125 * q @ k.T
    hmma_gemm<<<dim3(8, 8, B_SZ * KG), blk>>>(
        pY, pY + 256, pS4, nullptr, HD, 512, 512, N_SEQ, 0.125f,
        (long)N_SEQ * 512, 64, (long)N_SEQ * 512, 64, (long)N_SEQ * N_SEQ, KG);

    // 4) attention
    attn_kernel<<<dim3(16, 6, 8), blk, ATTN_SMEM>>>(pS4, pVt, mixl, pCtx);

    // 5) out = ctx @ W_proj.T + b_proj
    hmma_gemm<<<dim3(6, 64, 1), blk>>>(
        pCtx, W_proj, out, b_proj, DIM, DIM, DIM, DIM, 1.0f, 0, 0, 0, 0, 0, 1);
}

// round 12
// speedup vs baseline: 1.4846x; 1.0761x over previous
#include <cuda_runtime.h>
#include <cuda_bf16.h>
#include <cuda_fp16.h>
#include <cstdint>

// ---------------------------------------------------------------------------
// FiSHAttention: B=8, N=1024, dim=p=768, HEAD_DIM=64, K_GLOBAL=4, H_eff=12
// All intermediates fp16 (calibrated error model: out_err ~= 0.44 * operand
// unit rounding; quadrature budget ~5.3e-4 < 1e-3):
//   1) Yh   = fp16( x @ Wqkv[0:512].T )   (A f16-cvt, B hi/lo, 2-pass HMMA)
//   2) V16  = fp16( x @ Wv.T )            (same kernel)
//   2b) Vt  = per-head transpose of V16   (fp16)
//   3) S4h  = fp16( 0.125 * q @ k.T )     (pure-fp16 1-pass HMMA, 32 batched)
//      -> S4 is 64MB: fits L2, halves attn combine traffic
//   4) attn: combine+exp2 + PV 1-pass fp16 HMMA; ctx out fp16
//   5) out  = ctx16 @ Wproj.T + b_proj    (A fp16 preconv, B hi/lo, f32 out)
// ---------------------------------------------------------------------------

#define B_SZ   8
#define N_SEQ  1024
#define DIM    768
#define KG     4
#define HD     64
#define HEFF   12

__device__ __half g_Yh [B_SZ * N_SEQ * 512];
__device__ __half g_V16[B_SZ * N_SEQ * DIM];
__device__ __half g_c16[B_SZ * N_SEQ * DIM];
__device__ __half g_S4h[(size_t)B_SZ * KG * N_SEQ * N_SEQ];   // 64 MB
__device__ __half g_Vt [(size_t)B_SZ * HEFF * HD * N_SEQ];

// ------------------------------ helpers ------------------------------------
__device__ __forceinline__ uint32_t smem_u32(const void* p) {
    uint32_t a;
    asm("{ .reg .u64 t; cvta.to.shared.u64 t, %1; cvt.u32.u64 %0, t; }"
        : "=r"(a) : "l"(p));
    return a;
}
__device__ __forceinline__ void ldsm_x4(uint32_t& r0, uint32_t& r1,
                                        uint32_t& r2, uint32_t& r3, uint32_t addr) {
    asm volatile("ldmatrix.sync.aligned.m8n8.x4.shared.b16 {%0,%1,%2,%3}, [%4];"
        : "=r"(r0), "=r"(r1), "=r"(r2), "=r"(r3) : "r"(addr));
}
__device__ __forceinline__ void mma16816h(float* c, const uint32_t* a,
                                          const uint32_t* b) {
    asm volatile("mma.sync.aligned.m16n8k16.row.col.f32.f16.f16.f32 "
        "{%0,%1,%2,%3}, {%4,%5,%6,%7}, {%8,%9}, {%0,%1,%2,%3};"
        : "+f"(c[0]), "+f"(c[1]), "+f"(c[2]), "+f"(c[3])
        : "r"(a[0]), "r"(a[1]), "r"(a[2]), "r"(a[3]), "r"(b[0]), "r"(b[1]));
}
__device__ __forceinline__ uint32_t pack_h2(float x, float y) {
    return ((uint32_t)__half_as_ushort(__float2half(y)) << 16)
         | __half_as_ushort(__float2half(x));
}
__device__ __forceinline__ float4 ld4h(const __half* p) {
    uint2 u = *(const uint2*)p;
    __half2 a = *(__half2*)&u.x;
    __half2 b = *(__half2*)&u.y;
    float2 fa = __half22float2(a), fb = __half22float2(b);
    return make_float4(fa.x, fa.y, fb.x, fb.y);
}

__device__ __forceinline__ float fast_exp(float x) {
    x = fmaxf(x, -80.0f);
    const float L2E = 1.4426950408889634f;
    float t  = fmaf(x, L2E, 12582912.0f);
    float nf = t - 12582912.0f;
    int   ni = __float_as_int(t) - 0x4B400000;
    float f  = fmaf(x, L2E, -nf);
    f = fmaf(x, 1.9259629911266175e-8f, f);
    float p;
    p = 1.33335581e-3f;
    p = fmaf(p, f, 9.61812910e-3f);
    p = fmaf(p, f, 5.55041087e-2f);
    p = fmaf(p, f, 2.40226507e-1f);
    p = fmaf(p, f, 6.93147181e-1f);
    p = fmaf(p, f, 1.0f);
    return __int_as_float(__float_as_int(p) + (ni << 23));
}
__device__ __forceinline__ float fast_exp2(float y) {
    y = fmaxf(y, -100.0f);
    float t  = y + 12582912.0f;
    float nf = t - 12582912.0f;
    int   ni = __float_as_int(t) - 0x4B400000;
    float f  = y - nf;
    float p;
    p = 1.33335581e-3f;
    p = fmaf(p, f, 9.61812910e-3f);
    p = fmaf(p, f, 5.55041087e-2f);
    p = fmaf(p, f, 2.40226507e-1f);
    p = fmaf(p, f, 6.93147181e-1f);
    p = fmaf(p, f, 1.0f);
    return __int_as_float(__float_as_int(p) + (ni << 23));
}

#define BKC  32
#define TSTR 40

// ===========================================================================
// G1: f32 inputs (A f16-cvt single, B hi/lo fp16, 2-pass), fp16 output.
// Used for Y and V.
// ===========================================================================
__global__ __launch_bounds__(256) void gemm_f32_h16(
    const float* __restrict__ A, const float* __restrict__ B,
    __half* __restrict__ C, int K, int lda, int ldb, int ldc)
{
    const int row0 = blockIdx.y * 128;
    const int col0 = blockIdx.x * 128;

    __shared__ __half sA [128 * TSTR];
    __shared__ __half sBh[128 * TSTR], sBl[128 * TSTR];

    const int tid  = threadIdx.x;
    const int wid  = tid >> 5;
    const int lane = tid & 31;
    const int wm   = wid >> 1;
    const int wn   = wid & 1;
    const int a_r = lane & 15;
    const int a_k = (lane >> 4) << 3;
    const int b_r = (lane & 7) + ((lane >> 4) << 3);
    const int b_k = ((lane >> 3) & 1) << 3;

    const uint32_t uA  = smem_u32(sA);
    const uint32_t uBh = smem_u32(sBh), uBl = smem_u32(sBl);

    float acc[2][8][4];
    #pragma unroll
    for (int i = 0; i < 2; i++)
        #pragma unroll
        for (int j = 0; j < 8; j++)
            #pragma unroll
            for (int q = 0; q < 4; q++) acc[i][j][q] = 0.0f;

    const int nch = K / BKC;
    for (int t = 0; t < nch; t++) {
        #pragma unroll
        for (int it = 0; it < 4; it++) {
            int e = it * 256 + tid;
            int r = e >> 3;
            int c = (e & 7) << 2;
            float4 v = *(const float4*)&A[(long)(row0 + r) * lda + t * BKC + c];
            uint2 hv;
            hv.x = pack_h2(v.x, v.y);
            hv.y = pack_h2(v.z, v.w);
            *(uint2*)&sA[r * TSTR + c] = hv;
        }
        #pragma unroll
        for (int it = 0; it < 4; it++) {
            int e = it * 256 + tid;
            int r = e >> 3;
            int c = (e & 7) << 2;
            float4 v = *(const float4*)&B[(long)(col0 + r) * ldb + t * BKC + c];
            __half h0 = __float2half(v.x), h1 = __float2half(v.y);
            __half h2 = __float2half(v.z), h3 = __float2half(v.w);
            uint2 hv, lv;
            hv.x = ((uint32_t)__half_as_ushort(h1) << 16) | __half_as_ushort(h0);
            hv.y = ((uint32_t)__half_as_ushort(h3) << 16) | __half_as_ushort(h2);
            lv.x = pack_h2(v.x - __half2float(h0), v.y - __half2float(h1));
            lv.y = pack_h2(v.z - __half2float(h2), v.w - __half2float(h3));
            *(uint2*)&sBh[r * TSTR + c] = hv;
            *(uint2*)&sBl[r * TSTR + c] = lv;
        }
        __syncthreads();

        #pragma unroll
        for (int ks = 0; ks < 2; ks++) {
            const int k0 = ks * 16;
            const uint32_t aoff = (uint32_t)((wm * 32 + a_r) * TSTR + k0 + a_k) * 2;
            const uint32_t boff = (uint32_t)((wn * 64 + b_r) * TSTR + k0 + b_k) * 2;
            uint32_t af[2][4];
            ldsm_x4(af[0][0], af[0][1], af[0][2], af[0][3], uA + aoff);
            ldsm_x4(af[1][0], af[1][1], af[1][2], af[1][3], uA + aoff + 16 * TSTR * 2);
            uint32_t bh[8][2], bl[8][2];
            #pragma unroll
            for (int nb = 0; nb < 4; nb++) {
                ldsm_x4(bh[2*nb][0], bh[2*nb][1], bh[2*nb+1][0], bh[2*nb+1][1],
                        uBh + boff + nb * 16 * TSTR * 2);
                ldsm_x4(bl[2*nb][0], bl[2*nb][1], bl[2*nb+1][0], bl[2*nb+1][1],
                        uBl + boff + nb * 16 * TSTR * 2);
            }
            #pragma unroll
            for (int mf = 0; mf < 2; mf++)
                #pragma unroll
                for (int nf = 0; nf < 8; nf++) {
                    mma16816h(acc[mf][nf], af[mf], bh[nf]);
                    mma16816h(acc[mf][nf], af[mf], bl[nf]);
                }
        }
        __syncthreads();
    }

    const int qrow = lane >> 2;
    const int qcol = (lane & 3) << 1;
    #pragma unroll
    for (int mf = 0; mf < 2; mf++)
        #pragma unroll
        for (int half = 0; half < 2; half++) {
            long r = row0 + wm * 32 + mf * 16 + half * 8 + qrow;
            #pragma unroll
            for (int nf = 0; nf < 8; nf++) {
                int n = col0 + wn * 64 + nf * 8 + qcol;
                *(uint32_t*)&C[r * ldc + n] =
                    pack_h2(acc[mf][nf][half * 2 + 0], acc[mf][nf][half * 2 + 1]);
            }
        }
}

// ===========================================================================
// G2: pure fp16 in (1-pass), fp16 out, batched. Used for S4.
// ===========================================================================
__global__ __launch_bounds__(256) void gemm_h16_h16(
    const __half* __restrict__ A, const __half* __restrict__ B,
    __half* __restrict__ C, int K, int lda, int ldb, int ldc, float alpha,
    long sAo, long sAi, long sBo, long sBi, long sC, int innerMod)
{
    {
        int z = blockIdx.z;
        int outer = z / innerMod;
        int inner = z - outer * innerMod;
        A += (long)outer * sAo + (long)inner * sAi;
        B += (long)outer * sBo + (long)inner * sBi;
        C += (long)z * sC;
    }
    const int row0 = blockIdx.y * 128;
    const int col0 = blockIdx.x * 128;

    __shared__ __half sA[128 * TSTR];
    __shared__ __half sB[128 * TSTR];

    const int tid  = threadIdx.x;
    const int wid  = tid >> 5;
    const int lane = tid & 31;
    const int wm   = wid >> 1;
    const int wn   = wid & 1;
    const int a_r = lane & 15;
    const int a_k = (lane >> 4) << 3;
    const int b_r = (lane & 7) + ((lane >> 4) << 3);
    const int b_k = ((lane >> 3) & 1) << 3;

    const uint32_t uA = smem_u32(sA);
    const uint32_t uB = smem_u32(sB);

    float acc[2][8][4];
    #pragma unroll
    for (int i = 0; i < 2; i++)
        #pragma unroll
        for (int j = 0; j < 8; j++)
            #pragma unroll
            for (int q = 0; q < 4; q++) acc[i][j][q] = 0.0f;

    const int nch = K / BKC;
    for (int t = 0; t < nch; t++) {
        #pragma unroll
        for (int it = 0; it < 2; it++) {
            int e = it * 256 + tid;
            int r = e >> 2;
            int q = (e & 3) << 3;
            *(uint4*)&sA[r * TSTR + q] =
                *(const uint4*)&A[(long)(row0 + r) * lda + t * BKC + q];
        }
        #pragma unroll
        for (int it = 0; it < 2; it++) {
            int e = it * 256 + tid;
            int r = e >> 2;
            int q = (e & 3) << 3;
            *(uint4*)&sB[r * TSTR + q] =
                *(const uint4*)&B[(long)(col0 + r) * ldb + t * BKC + q];
        }
        __syncthreads();

        #pragma unroll
        for (int ks = 0; ks < 2; ks++) {
            const int k0 = ks * 16;
            const uint32_t aoff = (uint32_t)((wm * 32 + a_r) * TSTR + k0 + a_k) * 2;
            const uint32_t boff = (uint32_t)((wn * 64 + b_r) * TSTR + k0 + b_k) * 2;
            uint32_t af[2][4];
            ldsm_x4(af[0][0], af[0][1], af[0][2], af[0][3], uA + aoff);
            ldsm_x4(af[1][0], af[1][1], af[1][2], af[1][3], uA + aoff + 16 * TSTR * 2);
            uint32_t bv[8][2];
            #pragma unroll
            for (int nb = 0; nb < 4; nb++)
                ldsm_x4(bv[2*nb][0], bv[2*nb][1], bv[2*nb+1][0], bv[2*nb+1][1],
                        uB + boff + nb * 16 * TSTR * 2);
            #pragma unroll
            for (int mf = 0; mf < 2; mf++)
                #pragma unroll
                for (int nf = 0; nf < 8; nf++)
                    mma16816h(acc[mf][nf], af[mf], bv[nf]);
        }
        __syncthreads();
    }

    const int qrow = lane >> 2;
    const int qcol = (lane & 3) << 1;
    #pragma unroll
    for (int mf = 0; mf < 2; mf++)
        #pragma unroll
        for (int half = 0; half < 2; half++) {
            long r = row0 + wm * 32 + mf * 16 + half * 8 + qrow;
            #pragma unroll
            for (int nf = 0; nf < 8; nf++) {
                int n = col0 + wn * 64 + nf * 8 + qcol;
                *(uint32_t*)&C[r * ldc + n] =
                    pack_h2(alpha * acc[mf][nf][half * 2 + 0],
                            alpha * acc[mf][nf][half * 2 + 1]);
            }
        }
}

// ===========================================================================
// G3: A fp16 preconverted, B f32 (hi/lo, 2-pass), f32 out + bias. For proj.
// ===========================================================================
__global__ __launch_bounds__(256) void gemm_h16_f32(
    const __half* __restrict__ A, const float* __restrict__ B,
    float* __restrict__ C, const float* __restrict__ bias,
    int K, int lda, int ldb, int ldc)
{
    const int row0 = blockIdx.y * 128;
    const int col0 = blockIdx.x * 128;

    __shared__ __half sA [128 * TSTR];
    __shared__ __half sBh[128 * TSTR], sBl[128 * TSTR];

    const int tid  = threadIdx.x;
    const int wid  = tid >> 5;
    const int lane = tid & 31;
    const int wm   = wid >> 1;
    const int wn   = wid & 1;
    const int a_r = lane & 15;
    const int a_k = (lane >> 4) << 3;
    const int b_r = (lane & 7) + ((lane >> 4) << 3);
    const int b_k = ((lane >> 3) & 1) << 3;

    const uint32_t uA  = smem_u32(sA);
    const uint32_t uBh = smem_u32(sBh), uBl = smem_u32(sBl);

    float acc[2][8][4];
    #pragma unroll
    for (int i = 0; i < 2; i++)
        #pragma unroll
        for (int j = 0; j < 8; j++)
            #pragma unroll
            for (int q = 0; q < 4; q++) acc[i][j][q] = 0.0f;

    const int nch = K / BKC;
    for (int t = 0; t < nch; t++) {
        #pragma unroll
        for (int it = 0; it < 2; it++) {
            int e = it * 256 + tid;
            int r = e >> 2;
            int q = (e & 3) << 3;
            *(uint4*)&sA[r * TSTR + q] =
                *(const uint4*)&A[(long)(row0 + r) * lda + t * BKC + q];
        }
        #pragma unroll
        for (int it = 0; it < 4; it++) {
            int e = it * 256 + tid;
            int r = e >> 3;
            int c = (e & 7) << 2;
            float4 v = *(const float4*)&B[(long)(col0 + r) * ldb + t * BKC + c];
            __half h0 = __float2half(v.x), h1 = __float2half(v.y);
            __half h2 = __float2half(v.z), h3 = __float2half(v.w);
            uint2 hv, lv;
            hv.x = ((uint32_t)__half_as_ushort(h1) << 16) | __half_as_ushort(h0);
            hv.y = ((uint32_t)__half_as_ushort(h3) << 16) | __half_as_ushort(h2);
            lv.x = pack_h2(v.x - __half2float(h0), v.y - __half2float(h1));
            lv.y = pack_h2(v.z - __half2float(h2), v.w - __half2float(h3));
            *(uint2*)&sBh[r * TSTR + c] = hv;
            *(uint2*)&sBl[r * TSTR + c] = lv;
        }
        __syncthreads();

        #pragma unroll
        for (int ks = 0; ks < 2; ks++) {
            const int k0 = ks * 16;
            const uint32_t aoff = (uint32_t)((wm * 32 + a_r) * TSTR + k0 + a_k) * 2;
            const uint32_t boff = (uint32_t)((wn * 64 + b_r) * TSTR + k0 + b_k) * 2;
            uint32_t af[2][4];
            ldsm_x4(af[0][0], af[0][1], af[0][2], af[0][3], uA + aoff);
            ldsm_x4(af[1][0], af[1][1], af[1][2], af[1][3], uA + aoff + 16 * TSTR * 2);
            uint32_t bh[8][2], bl[8][2];
            #pragma unroll
            for (int nb = 0; nb < 4; nb++) {
                ldsm_x4(bh[2*nb][0], bh[2*nb][1], bh[2*nb+1][0], bh[2*nb+1][1],
                        uBh + boff + nb * 16 * TSTR * 2);
                ldsm_x4(bl[2*nb][0], bl[2*nb][1], bl[2*nb+1][0], bl[2*nb+1][1],
                        uBl + boff + nb * 16 * TSTR * 2);
            }
            #pragma unroll
            for (int mf = 0; mf < 2; mf++)
                #pragma unroll
                for (int nf = 0; nf < 8; nf++) {
                    mma16816h(acc[mf][nf], af[mf], bh[nf]);
                    mma16816h(acc[mf][nf], af[mf], bl[nf]);
                }
        }
        __syncthreads();
    }

    const int qrow = lane >> 2;
    const int qcol = (lane & 3) << 1;
    #pragma unroll
    for (int mf = 0; mf < 2; mf++)
        #pragma unroll
        for (int half = 0; half < 2; half++) {
            long r = row0 + wm * 32 + mf * 16 + half * 8 + qrow;
            #pragma unroll
            for (int nf = 0; nf < 8; nf++) {
                int n = col0 + wn * 64 + nf * 8 + qcol;
                float2 o;
                o.x = acc[mf][nf][half * 2 + 0] + bias[n];
                o.y = acc[mf][nf][half * 2 + 1] + bias[n + 1];
                *(float2*)&C[r * ldc + n] = o;
            }
        }
}

// ===========================================================================
// V transpose (fp16 in, fp16 out).
// ===========================================================================
__global__ __launch_bounds__(256) void vconvert(
    const __half* __restrict__ V, __half* __restrict__ Vt)
{
    const int j0   = blockIdx.x * 64;
    const int bhid = blockIdx.y;
    const int b    = bhid / HEFF;
    const int h    = bhid - b * HEFF;

    __shared__ __half sT[64][72];
    const int tid = threadIdx.x;

    #pragma unroll
    for (int it = 0; it < 4; it++) {
        int e = it * 256 + tid;
        int j = e >> 4, dq = (e & 15) << 2;
        uint2 u = *(const uint2*)&V[((long)b * N_SEQ + j0 + j) * DIM + h * HD + dq];
        __half2 a = *(__half2*)&u.x;
        __half2 c = *(__half2*)&u.y;
        sT[dq + 0][j] = __low2half(a);  sT[dq + 1][j] = __high2half(a);
        sT[dq + 2][j] = __low2half(c);  sT[dq + 3][j] = __high2half(c);
    }
    __syncthreads();

    const int d = tid >> 2, jseg = (tid & 3) << 4;
    size_t dst = ((size_t)bhid * HD + d) * N_SEQ + j0 + jseg;
    *(uint4*)&Vt[dst]     = *(uint4*)&sT[d][jseg];
    *(uint4*)&Vt[dst + 8] = *(uint4*)&sT[d][jseg + 8];
}

// ===========================================================================
// Attention: 2 heads/CTA, S4 fp16 in, P fp16, V fp16, 1-pass PV MMA,
// ctx fp16 out. Grid (16, 6, 8), 256 threads. smem ~37.4KB.
// ===========================================================================
#define PBY 9216
#define OFF_V 0
#define OFF_P (2 * PBY)
#define OFF_SUM (4 * PBY)
#define OFF_MIX (OFF_SUM + 512)
#define ATTN_SMEM (OFF_MIX + 64)

__global__ __launch_bounds__(256, 2) void attn_kernel(
    const __half* __restrict__ S4, const __half* __restrict__ Vt,
    const float* __restrict__ mixl, __half* __restrict__ ctx)
{
    const int ib = blockIdx.x;
    const int hg = blockIdx.y;
    const int b  = blockIdx.z;

    extern __shared__ char sm[];
    const uint32_t sb = smem_u32(sm);
    float* sSum = (float*)(sm + OFF_SUM);
    float* sMix = (float*)(sm + OFF_MIX);

    const int tid  = threadIdx.x;
    const int wid  = tid >> 5;
    const int lane = tid & 31;
    const int wr   = wid >> 1;
    const int wc   = wid & 1;
    const int a_r  = lane & 15;
    const int a_k  = (lane >> 4) << 3;
    const int b_r  = (lane & 7) + ((lane >> 4) << 3);
    const int b_k  = ((lane >> 3) & 1) << 3;

    if (tid < 128) sSum[tid] = 0.0f;
    if (tid < 8) {
        int hh = tid >> 2, k = tid & 3;
        const float* ml = mixl + (hg * 2 + hh) * 4;
        float l0 = ml[0], l1 = ml[1], l2 = ml[2], l3 = ml[3];
        float m  = fmaxf(fmaxf(l0, l1), fmaxf(l2, l3));
        float e0 = fast_exp(l0 - m), e1 = fast_exp(l1 - m);
        float e2 = fast_exp(l2 - m), e3 = fast_exp(l3 - m);
        float s  = e0 + e1 + e2 + e3;
        float mine = (k == 0) ? e0 : (k == 1) ? e1 : (k == 2) ? e2 : e3;
        sMix[hh * 4 + k] = (mine / s) * 1.4426950408889634f;
    }

    const int i0   = ib * 64;
    const int arow = tid >> 2;
    const int aq   = tid & 3;
    const __half* S4b = S4 + (size_t)b * KG * N_SEQ * N_SEQ;
    const long   PL  = (long)N_SEQ * N_SEQ;
    const size_t vbase0 = ((size_t)(b * HEFF + hg * 2 + 0)) * HD * N_SEQ;
    const size_t vbase1 = ((size_t)(b * HEFF + hg * 2 + 1)) * HD * N_SEQ;

    float acc[2][4][4];
    #pragma unroll
    for (int i = 0; i < 2; i++)
        #pragma unroll
        for (int j = 0; j < 4; j++)
            #pragma unroll
            for (int q = 0; q < 4; q++) acc[i][j][q] = 0.0f;

    for (int j0 = 0; j0 < N_SEQ; j0 += 64) {
        __syncthreads();

        // ---- load V fp16 tiles (2 buffers x 512 uint4) ---------------------
        #pragma unroll
        for (int it = 0; it < 4; it++) {
            int idx = it * 256 + tid;
            int bufid = idx >> 9;
            int r = (idx >> 3) & 63;
            int q = idx & 7;
            size_t so = (bufid ? vbase1 : vbase0) + (size_t)r * N_SEQ + j0 + q * 8;
            *(uint4*)(sm + OFF_V + bufid * PBY + (r * 72 + q * 8) * 2) =
                *(const uint4*)&Vt[so];
        }

        // ---- phase A: combine fp16 planes + exp2, store P fp16 -------------
        {
            const float mx00 = sMix[0], mx01 = sMix[1], mx02 = sMix[2], mx03 = sMix[3];
            const float mx10 = sMix[4], mx11 = sMix[5], mx12 = sMix[6], mx13 = sMix[7];
            const __half* base = S4b + (long)(i0 + arow) * N_SEQ + j0 + aq * 16;
            float s0 = 0.0f, s1 = 0.0f;
            #pragma unroll
            for (int c = 0; c < 4; c++) {
                float4 a  = ld4h(base + c * 4);
                float4 p1 = ld4h(base + PL + c * 4);
                float4 p2 = ld4h(base + 2 * PL + c * 4);
                float4 p3 = ld4h(base + 3 * PL + c * 4);
                const uint32_t po = (uint32_t)(arow * 72 + aq * 16 + c * 4) * 2;
                #pragma unroll
                for (int hh = 0; hh < 2; hh++) {
                    float m0 = hh ? mx10 : mx00, m1 = hh ? mx11 : mx01;
                    float m2 = hh ? mx12 : mx02, m3 = hh ? mx13 : mx03;
                    float q0 = fast_exp2(fmaf(m3, p3.x, fmaf(m2, p2.x, fmaf(m1, p1.x, m0 * a.x))));
                    float q1 = fast_exp2(fmaf(m3, p3.y, fmaf(m2, p2.y, fmaf(m1, p1.y, m0 * a.y))));
                    float q2 = fast_exp2(fmaf(m3, p3.z, fmaf(m2, p2.z, fmaf(m1, p1.z, m0 * a.z))));
                    float q3 = fast_exp2(fmaf(m3, p3.w, fmaf(m2, p2.w, fmaf(m1, p1.w, m0 * a.w))));
                    if (hh) s1 += (q0 + q1) + (q2 + q3);
                    else    s0 += (q0 + q1) + (q2 + q3);
                    uint2 hv;
                    hv.x = pack_h2(q0, q1);
                    hv.y = pack_h2(q2, q3);
                    *(uint2*)(sm + OFF_P + hh * PBY + po) = hv;
                }
            }
            s0 += __shfl_xor_sync(0xffffffffu, s0, 1);
            s0 += __shfl_xor_sync(0xffffffffu, s0, 2);
            s1 += __shfl_xor_sync(0xffffffffu, s1, 1);
            s1 += __shfl_xor_sync(0xffffffffu, s1, 2);
            if (aq == 0) {
                sSum[arow]      += s0;
                sSum[64 + arow] += s1;
            }
        }
        __syncthreads();

        // ---- MMA: both heads, 1-pass fp16 (P @ V) --------------------------
        #pragma unroll
        for (int hh = 0; hh < 2; hh++) {
            const uint32_t uP = sb + OFF_P + hh * PBY;
            const uint32_t uV = sb + OFF_V + hh * PBY;
            #pragma unroll
            for (int ks = 0; ks < 4; ks++) {
                const int k0 = ks * 16;
                const uint32_t aoff = (uint32_t)((wr * 16 + a_r) * 72 + k0 + a_k) * 2;
                const uint32_t boff = (uint32_t)((wc * 32 + b_r) * 72 + k0 + b_k) * 2;
                uint32_t ah[4];
                ldsm_x4(ah[0], ah[1], ah[2], ah[3], uP + aoff);
                uint32_t bv[4][2];
                #pragma unroll
                for (int nb = 0; nb < 2; nb++)
                    ldsm_x4(bv[2*nb][0], bv[2*nb][1], bv[2*nb+1][0], bv[2*nb+1][1],
                            uV + boff + nb * 16 * 72 * 2);
                #pragma unroll
                for (int nf = 0; nf < 4; nf++)
                    mma16816h(acc[hh][nf], ah, bv[nf]);
            }
        }
    }
    __syncthreads();

    // ---- epilogue: normalize, write ctx fp16 -------------------------------
    const int qrow = lane >> 2;
    const int qcol = (lane & 3) << 1;
    #pragma unroll
    for (int hh = 0; hh < 2; hh++)
        #pragma unroll
        for (int half = 0; half < 2; half++) {
            int r = wr * 16 + half * 8 + qrow;
            float inv = 1.0f / sSum[hh * 64 + r];
            long obase = ((long)b * N_SEQ + i0 + r) * DIM + (hg * 2 + hh) * HD;
            #pragma unroll
            for (int nf = 0; nf < 4; nf++) {
                int n = wc * 32 + nf * 8 + qcol;
                *(uint32_t*)&ctx[obase + n] =
                    pack_h2(acc[hh][nf][half * 2 + 0] * inv,
                            acc[hh][nf][half * 2 + 1] * inv);
            }
        }
}

// ---------------------------------------------------------------------------
extern "C" void kernel_launch(void* const* d_in, const int* in_sizes, int n_in,
                              void* d_out, int out_size)
{
    const float* x      = (const float*)d_in[0];
    const float* W_qkv  = (const float*)d_in[1];
    const float* W_v    = (const float*)d_in[2];
    const float* W_proj = (const float*)d_in[3];
    const float* b_proj = (const float*)d_in[4];
    const float* mixl   = (const float*)d_in[5];
    float* out = (float*)d_out;

    __half *pYh, *pV16, *pc16, *pS4h, *pVt;
    cudaGetSymbolAddress((void**)&pYh,  g_Yh);
    cudaGetSymbolAddress((void**)&pV16, g_V16);
    cudaGetSymbolAddress((void**)&pc16, g_c16);
    cudaGetSymbolAddress((void**)&pS4h, g_S4h);
    cudaGetSymbolAddress((void**)&pVt,  g_Vt);

    static bool attrDone = false;
    if (!attrDone) {
        cudaFuncSetAttribute(attn_kernel,
                             cudaFuncAttributeMaxDynamicSharedMemorySize, ATTN_SMEM);
        attrDone = true;
    }

    dim3 blk(256);

    // 1) Yh = fp16( x @ W_qkv[0:512].T )
    gemm_f32_h16<<<dim3(4, 64, 1), blk>>>(x, W_qkv, pYh, DIM, DIM, DIM, 512);

    // 2) V16 = fp16( x @ W_v.T )
    gemm_f32_h16<<<dim3(6, 64, 1), blk>>>(x, W_v, pV16, DIM, DIM, DIM, DIM);

    // 2b) V16 -> per-head transposed Vt
    vconvert<<<dim3(16, 96, 1), blk>>>(pV16, pVt);

    // 3) S4h = fp16( 0.125 * q @ k.T )   pure fp16, 32 batched
    gemm_h16_h16<<<dim3(8, 8, B_SZ * KG), blk>>>(
        pYh, pYh + 256, pS4h, HD, 512, 512, N_SEQ, 0.125f,
        (long)N_SEQ * 512, 64, (long)N_SEQ * 512, 64, (long)N_SEQ * N_SEQ, KG);

    // 4) attention -> ctx fp16
    attn_kernel<<<dim3(16, 6, 8), blk, ATTN_SMEM>>>(pS4h, pVt, mixl, pc16);

    // 5) out = ctx16 @ W_proj.T + b_proj
    gemm_h16_f32<<<dim3(6, 64, 1), blk>>>(pc16, W_proj, out, b_proj,
                                          DIM, DIM, DIM, DIM);
}

// round 13
// speedup vs baseline: 1.7254x; 1.1622x over previous
#include <cuda_runtime.h>
#include <cuda_bf16.h>
#include <cuda_fp16.h>
#include <cstdint>

// ---------------------------------------------------------------------------
// FiSHAttention: B=8, N=1024, dim=p=768, HEAD_DIM=64, K_GLOBAL=4, H_eff=12
// Pure-fp16 tensor-core pipeline (error model: out_err ~= 0.44*unit rounding
// per single-precision operand; quadrature budget ~5.4e-4 < 1e-3):
//   1) Yh   = fp16( x @ Wqkv[0:512].T )   1-pass fp16 HMMA
//   2) V16  = fp16( x @ Wv.T )            1-pass
//   2b) Vt  = per-head transpose of V16
//   3) S4h  = fp16( 0.125 * q @ k.T )     1-pass, 32 batched (64MB, L2-fits)
//   4) attn: cp.async-pipelined S4 stage + double-buffered V; combine+exp2
//      from smem; PV 1-pass fp16 HMMA; ctx fp16
//   5) out  = ctx16 @ Wproj.T + b_proj    1-pass, f32 out
// ---------------------------------------------------------------------------

#define B_SZ   8
#define N_SEQ  1024
#define DIM    768
#define KG     4
#define HD     64
#define HEFF   12

__device__ __half g_Yh [B_SZ * N_SEQ * 512];
__device__ __half g_V16[B_SZ * N_SEQ * DIM];
__device__ __half g_c16[B_SZ * N_SEQ * DIM];
__device__ __half g_S4h[(size_t)B_SZ * KG * N_SEQ * N_SEQ];   // 64 MB
__device__ __half g_Vt [(size_t)B_SZ * HEFF * HD * N_SEQ];

// ------------------------------ helpers ------------------------------------
__device__ __forceinline__ uint32_t smem_u32(const void* p) {
    uint32_t a;
    asm("{ .reg .u64 t; cvta.to.shared.u64 t, %1; cvt.u32.u64 %0, t; }"
        : "=r"(a) : "l"(p));
    return a;
}
__device__ __forceinline__ void ldsm_x4(uint32_t& r0, uint32_t& r1,
                                        uint32_t& r2, uint32_t& r3, uint32_t addr) {
    asm volatile("ldmatrix.sync.aligned.m8n8.x4.shared.b16 {%0,%1,%2,%3}, [%4];"
        : "=r"(r0), "=r"(r1), "=r"(r2), "=r"(r3) : "r"(addr));
}
__device__ __forceinline__ void mma16816h(float* c, const uint32_t* a,
                                          const uint32_t* b) {
    asm volatile("mma.sync.aligned.m16n8k16.row.col.f32.f16.f16.f32 "
        "{%0,%1,%2,%3}, {%4,%5,%6,%7}, {%8,%9}, {%0,%1,%2,%3};"
        : "+f"(c[0]), "+f"(c[1]), "+f"(c[2]), "+f"(c[3])
        : "r"(a[0]), "r"(a[1]), "r"(a[2]), "r"(a[3]), "r"(b[0]), "r"(b[1]));
}
__device__ __forceinline__ void cp_async16(uint32_t s, const void* g) {
    asm volatile("cp.async.cg.shared.global [%0], [%1], 16;" :: "r"(s), "l"(g));
}
__device__ __forceinline__ void cp_commit() {
    asm volatile("cp.async.commit_group;" ::: "memory");
}
template<int N> __device__ __forceinline__ void cp_wait() {
    asm volatile("cp.async.wait_group %0;" :: "n"(N) : "memory");
}
__device__ __forceinline__ uint32_t pack_h2(float x, float y) {
    return ((uint32_t)__half_as_ushort(__float2half(y)) << 16)
         | __half_as_ushort(__float2half(x));
}

__device__ __forceinline__ float fast_exp(float x) {
    x = fmaxf(x, -80.0f);
    const float L2E = 1.4426950408889634f;
    float t  = fmaf(x, L2E, 12582912.0f);
    float nf = t - 12582912.0f;
    int   ni = __float_as_int(t) - 0x4B400000;
    float f  = fmaf(x, L2E, -nf);
    f = fmaf(x, 1.9259629911266175e-8f, f);
    float p;
    p = 1.33335581e-3f;
    p = fmaf(p, f, 9.61812910e-3f);
    p = fmaf(p, f, 5.55041087e-2f);
    p = fmaf(p, f, 2.40226507e-1f);
    p = fmaf(p, f, 6.93147181e-1f);
    p = fmaf(p, f, 1.0f);
    return __int_as_float(__float_as_int(p) + (ni << 23));
}
__device__ __forceinline__ float fast_exp2(float y) {
    y = fmaxf(y, -100.0f);
    float t  = y + 12582912.0f;
    float nf = t - 12582912.0f;
    int   ni = __float_as_int(t) - 0x4B400000;
    float f  = y - nf;
    float p;
    p = 1.33335581e-3f;
    p = fmaf(p, f, 9.61812910e-3f);
    p = fmaf(p, f, 5.55041087e-2f);
    p = fmaf(p, f, 2.40226507e-1f);
    p = fmaf(p, f, 6.93147181e-1f);
    p = fmaf(p, f, 1.0f);
    return __int_as_float(__float_as_int(p) + (ni << 23));
}

#define BKC  32
#define TSTR 40

// ===========================================================================
// G1: f32 in (both cvt to single fp16), fp16 out, 1-pass. Used for Y, V.
// ===========================================================================
__global__ __launch_bounds__(256) void gemm_f32_h16(
    const float* __restrict__ A, const float* __restrict__ B,
    __half* __restrict__ C, int K, int lda, int ldb, int ldc)
{
    const int row0 = blockIdx.y * 128;
    const int col0 = blockIdx.x * 128;

    __shared__ __half sA[128 * TSTR];
    __shared__ __half sB[128 * TSTR];

    const int tid  = threadIdx.x;
    const int wid  = tid >> 5;
    const int lane = tid & 31;
    const int wm   = wid >> 1;
    const int wn   = wid & 1;
    const int a_r = lane & 15;
    const int a_k = (lane >> 4) << 3;
    const int b_r = (lane & 7) + ((lane >> 4) << 3);
    const int b_k = ((lane >> 3) & 1) << 3;

    const uint32_t uA = smem_u32(sA);
    const uint32_t uB = smem_u32(sB);

    float acc[2][8][4];
    #pragma unroll
    for (int i = 0; i < 2; i++)
        #pragma unroll
        for (int j = 0; j < 8; j++)
            #pragma unroll
            for (int q = 0; q < 4; q++) acc[i][j][q] = 0.0f;

    const int nch = K / BKC;
    for (int t = 0; t < nch; t++) {
        #pragma unroll
        for (int m = 0; m < 2; m++) {
            const float* src = m ? B : A;
            const int    ld  = m ? ldb : lda;
            const int    rb  = m ? col0 : row0;
            __half* dst = m ? sB : sA;
            #pragma unroll
            for (int it = 0; it < 4; it++) {
                int e = it * 256 + tid;
                int r = e >> 3;
                int c = (e & 7) << 2;
                float4 v = *(const float4*)&src[(long)(rb + r) * ld + t * BKC + c];
                uint2 hv;
                hv.x = pack_h2(v.x, v.y);
                hv.y = pack_h2(v.z, v.w);
                *(uint2*)&dst[r * TSTR + c] = hv;
            }
        }
        __syncthreads();

        #pragma unroll
        for (int ks = 0; ks < 2; ks++) {
            const int k0 = ks * 16;
            const uint32_t aoff = (uint32_t)((wm * 32 + a_r) * TSTR + k0 + a_k) * 2;
            const uint32_t boff = (uint32_t)((wn * 64 + b_r) * TSTR + k0 + b_k) * 2;
            uint32_t af[2][4];
            ldsm_x4(af[0][0], af[0][1], af[0][2], af[0][3], uA + aoff);
            ldsm_x4(af[1][0], af[1][1], af[1][2], af[1][3], uA + aoff + 16 * TSTR * 2);
            uint32_t bv[8][2];
            #pragma unroll
            for (int nb = 0; nb < 4; nb++)
                ldsm_x4(bv[2*nb][0], bv[2*nb][1], bv[2*nb+1][0], bv[2*nb+1][1],
                        uB + boff + nb * 16 * TSTR * 2);
            #pragma unroll
            for (int mf = 0; mf < 2; mf++)
                #pragma unroll
                for (int nf = 0; nf < 8; nf++)
                    mma16816h(acc[mf][nf], af[mf], bv[nf]);
        }
        __syncthreads();
    }

    const int qrow = lane >> 2;
    const int qcol = (lane & 3) << 1;
    #pragma unroll
    for (int mf = 0; mf < 2; mf++)
        #pragma unroll
        for (int half = 0; half < 2; half++) {
            long r = row0 + wm * 32 + mf * 16 + half * 8 + qrow;
            #pragma unroll
            for (int nf = 0; nf < 8; nf++) {
                int n = col0 + wn * 64 + nf * 8 + qcol;
                *(uint32_t*)&C[r * ldc + n] =
                    pack_h2(acc[mf][nf][half * 2 + 0], acc[mf][nf][half * 2 + 1]);
            }
        }
}

// ===========================================================================
// G2: pure fp16 in, fp16 out, batched, 1-pass. Used for S4.
// ===========================================================================
__global__ __launch_bounds__(256) void gemm_h16_h16(
    const __half* __restrict__ A, const __half* __restrict__ B,
    __half* __restrict__ C, int K, int lda, int ldb, int ldc, float alpha,
    long sAo, long sAi, long sBo, long sBi, long sC, int innerMod)
{
    {
        int z = blockIdx.z;
        int outer = z / innerMod;
        int inner = z - outer * innerMod;
        A += (long)outer * sAo + (long)inner * sAi;
        B += (long)outer * sBo + (long)inner * sBi;
        C += (long)z * sC;
    }
    const int row0 = blockIdx.y * 128;
    const int col0 = blockIdx.x * 128;

    __shared__ __half sA[128 * TSTR];
    __shared__ __half sB[128 * TSTR];

    const int tid  = threadIdx.x;
    const int wid  = tid >> 5;
    const int lane = tid & 31;
    const int wm   = wid >> 1;
    const int wn   = wid & 1;
    const int a_r = lane & 15;
    const int a_k = (lane >> 4) << 3;
    const int b_r = (lane & 7) + ((lane >> 4) << 3);
    const int b_k = ((lane >> 3) & 1) << 3;

    const uint32_t uA = smem_u32(sA);
    const uint32_t uB = smem_u32(sB);

    float acc[2][8][4];
    #pragma unroll
    for (int i = 0; i < 2; i++)
        #pragma unroll
        for (int j = 0; j < 8; j++)
            #pragma unroll
            for (int q = 0; q < 4; q++) acc[i][j][q] = 0.0f;

    const int nch = K / BKC;
    for (int t = 0; t < nch; t++) {
        #pragma unroll
        for (int it = 0; it < 2; it++) {
            int e = it * 256 + tid;
            int r = e >> 2;
            int q = (e & 3) << 3;
            *(uint4*)&sA[r * TSTR + q] =
                *(const uint4*)&A[(long)(row0 + r) * lda + t * BKC + q];
        }
        #pragma unroll
        for (int it = 0; it < 2; it++) {
            int e = it * 256 + tid;
            int r = e >> 2;
            int q = (e & 3) << 3;
            *(uint4*)&sB[r * TSTR + q] =
                *(const uint4*)&B[(long)(col0 + r) * ldb + t * BKC + q];
        }
        __syncthreads();

        #pragma unroll
        for (int ks = 0; ks < 2; ks++) {
            const int k0 = ks * 16;
            const uint32_t aoff = (uint32_t)((wm * 32 + a_r) * TSTR + k0 + a_k) * 2;
            const uint32_t boff = (uint32_t)((wn * 64 + b_r) * TSTR + k0 + b_k) * 2;
            uint32_t af[2][4];
            ldsm_x4(af[0][0], af[0][1], af[0][2], af[0][3], uA + aoff);
            ldsm_x4(af[1][0], af[1][1], af[1][2], af[1][3], uA + aoff + 16 * TSTR * 2);
            uint32_t bv[8][2];
            #pragma unroll
            for (int nb = 0; nb < 4; nb++)
                ldsm_x4(bv[2*nb][0], bv[2*nb][1], bv[2*nb+1][0], bv[2*nb+1][1],
                        uB + boff + nb * 16 * TSTR * 2);
            #pragma unroll
            for (int mf = 0; mf < 2; mf++)
                #pragma unroll
                for (int nf = 0; nf < 8; nf++)
                    mma16816h(acc[mf][nf], af[mf], bv[nf]);
        }
        __syncthreads();
    }

    const int qrow = lane >> 2;
    const int qcol = (lane & 3) << 1;
    #pragma unroll
    for (int mf = 0; mf < 2; mf++)
        #pragma unroll
        for (int half = 0; half < 2; half++) {
            long r = row0 + wm * 32 + mf * 16 + half * 8 + qrow;
            #pragma unroll
            for (int nf = 0; nf < 8; nf++) {
                int n = col0 + wn * 64 + nf * 8 + qcol;
                *(uint32_t*)&C[r * ldc + n] =
                    pack_h2(alpha * acc[mf][nf][half * 2 + 0],
                            alpha * acc[mf][nf][half * 2 + 1]);
            }
        }
}

// ===========================================================================
// G3: A fp16 preconv, B f32->f16 single, f32 out + bias, 1-pass. For proj.
// ===========================================================================
__global__ __launch_bounds__(256) void gemm_h16_f32(
    const __half* __restrict__ A, const float* __restrict__ B,
    float* __restrict__ C, const float* __restrict__ bias,
    int K, int lda, int ldb, int ldc)
{
    const int row0 = blockIdx.y * 128;
    const int col0 = blockIdx.x * 128;

    __shared__ __half sA[128 * TSTR];
    __shared__ __half sB[128 * TSTR];

    const int tid  = threadIdx.x;
    const int wid  = tid >> 5;
    const int lane = tid & 31;
    const int wm   = wid >> 1;
    const int wn   = wid & 1;
    const int a_r = lane & 15;
    const int a_k = (lane >> 4) << 3;
    const int b_r = (lane & 7) + ((lane >> 4) << 3);
    const int b_k = ((lane >> 3) & 1) << 3;

    const uint32_t uA = smem_u32(sA);
    const uint32_t uB = smem_u32(sB);

    float acc[2][8][4];
    #pragma unroll
    for (int i = 0; i < 2; i++)
        #pragma unroll
        for (int j = 0; j < 8; j++)
            #pragma unroll
            for (int q = 0; q < 4; q++) acc[i][j][q] = 0.0f;

    const int nch = K / BKC;
    for (int t = 0; t < nch; t++) {
        #pragma unroll
        for (int it = 0; it < 2; it++) {
            int e = it * 256 + tid;
            int r = e >> 2;
            int q = (e & 3) << 3;
            *(uint4*)&sA[r * TSTR + q] =
                *(const uint4*)&A[(long)(row0 + r) * lda + t * BKC + q];
        }
        #pragma unroll
        for (int it = 0; it < 4; it++) {
            int e = it * 256 + tid;
            int r = e >> 3;
            int c = (e & 7) << 2;
            float4 v = *(const float4*)&B[(long)(col0 + r) * ldb + t * BKC + c];
            uint2 hv;
            hv.x = pack_h2(v.x, v.y);
            hv.y = pack_h2(v.z, v.w);
            *(uint2*)&sB[r * TSTR + c] = hv;
        }
        __syncthreads();

        #pragma unroll
        for (int ks = 0; ks < 2; ks++) {
            const int k0 = ks * 16;
            const uint32_t aoff = (uint32_t)((wm * 32 + a_r) * TSTR + k0 + a_k) * 2;
            const uint32_t boff = (uint32_t)((wn * 64 + b_r) * TSTR + k0 + b_k) * 2;
            uint32_t af[2][4];
            ldsm_x4(af[0][0], af[0][1], af[0][2], af[0][3], uA + aoff);
            ldsm_x4(af[1][0], af[1][1], af[1][2], af[1][3], uA + aoff + 16 * TSTR * 2);
            uint32_t bv[8][2];
            #pragma unroll
            for (int nb = 0; nb < 4; nb++)
                ldsm_x4(bv[2*nb][0], bv[2*nb][1], bv[2*nb+1][0], bv[2*nb+1][1],
                        uB + boff + nb * 16 * TSTR * 2);
            #pragma unroll
            for (int mf = 0; mf < 2; mf++)
                #pragma unroll
                for (int nf = 0; nf < 8; nf++)
                    mma16816h(acc[mf][nf], af[mf], bv[nf]);
        }
        __syncthreads();
    }

    const int qrow = lane >> 2;
    const int qcol = (lane & 3) << 1;
    #pragma unroll
    for (int mf = 0; mf < 2; mf++)
        #pragma unroll
        for (int half = 0; half < 2; half++) {
            long r = row0 + wm * 32 + mf * 16 + half * 8 + qrow;
            #pragma unroll
            for (int nf = 0; nf < 8; nf++) {
                int n = col0 + wn * 64 + nf * 8 + qcol;
                float2 o;
                o.x = acc[mf][nf][half * 2 + 0] + bias[n];
                o.y = acc[mf][nf][half * 2 + 1] + bias[n + 1];
                *(float2*)&C[r * ldc + n] = o;
            }
        }
}

// ===========================================================================
// V transpose (fp16 in/out).
// ===========================================================================
__global__ __launch_bounds__(256) void vconvert(
    const __half* __restrict__ V, __half* __restrict__ Vt)
{
    const int j0   = blockIdx.x * 64;
    const int bhid = blockIdx.y;
    const int b    = bhid / HEFF;
    const int h    = bhid - b * HEFF;

    __shared__ __half sT[64][72];
    const int tid = threadIdx.x;

    #pragma unroll
    for (int it = 0; it < 4; it++) {
        int e = it * 256 + tid;
        int j = e >> 4, dq = (e & 15) << 2;
        uint2 u = *(const uint2*)&V[((long)b * N_SEQ + j0 + j) * DIM + h * HD + dq];
        __half2 a = *(__half2*)&u.x;
        __half2 c = *(__half2*)&u.y;
        sT[dq + 0][j] = __low2half(a);  sT[dq + 1][j] = __high2half(a);
        sT[dq + 2][j] = __low2half(c);  sT[dq + 3][j] = __high2half(c);
    }
    __syncthreads();

    const int d = tid >> 2, jseg = (tid & 3) << 4;
    size_t dst = ((size_t)bhid * HD + d) * N_SEQ + j0 + jseg;
    *(uint4*)&Vt[dst]     = *(uint4*)&sT[d][jseg];
    *(uint4*)&Vt[dst + 8] = *(uint4*)&sT[d][jseg + 8];
}

// ===========================================================================
// Attention v8: cp.async pipelined. 2 heads/CTA. Grid (16, 6, 8), 256 thr.
// smem: V double-buffered (4x9216) + P (2x9216) + S4 stage (4x64x72 fp16)
//       + sums/mix = ~92.7KB -> 2 CTA/SM.
// Per tile: wait(stage,V) -> phase A from smem -> sync -> issue next tile's
// cp.async (overlaps MMA) -> MMA.
// ===========================================================================
#define PBY 9216
#define OFF_V 0                     // [parity][head] 4 x PBY
#define OFF_P (4 * PBY)             // [head] 2 x PBY
#define OFF_S (6 * PBY)             // stage: 4 planes x 64 x 72 fp16 = 36864
#define OFF_SUM (OFF_S + 36864)
#define OFF_MIX (OFF_SUM + 512)
#define ATTN_SMEM (OFF_MIX + 64)

__global__ __launch_bounds__(256, 2) void attn_kernel(
    const __half* __restrict__ S4, const __half* __restrict__ Vt,
    const float* __restrict__ mixl, __half* __restrict__ ctx)
{
    const int ib = blockIdx.x;
    const int hg = blockIdx.y;
    const int b  = blockIdx.z;

    extern __shared__ char sm[];
    const uint32_t sb = smem_u32(sm);
    float* sSum = (float*)(sm + OFF_SUM);
    float* sMix = (float*)(sm + OFF_MIX);
    const __half* sStage = (const __half*)(sm + OFF_S);

    const int tid  = threadIdx.x;
    const int wid  = tid >> 5;
    const int lane = tid & 31;
    const int wr   = wid >> 1;
    const int wc   = wid & 1;
    const int a_r  = lane & 15;
    const int a_k  = (lane >> 4) << 3;
    const int b_r  = (lane & 7) + ((lane >> 4) << 3);
    const int b_k  = ((lane >> 3) & 1) << 3;

    if (tid < 128) sSum[tid] = 0.0f;
    if (tid < 8) {
        int hh = tid >> 2, k = tid & 3;
        const float* ml = mixl + (hg * 2 + hh) * 4;
        float l0 = ml[0], l1 = ml[1], l2 = ml[2], l3 = ml[3];
        float m  = fmaxf(fmaxf(l0, l1), fmaxf(l2, l3));
        float e0 = fast_exp(l0 - m), e1 = fast_exp(l1 - m);
        float e2 = fast_exp(l2 - m), e3 = fast_exp(l3 - m);
        float s  = e0 + e1 + e2 + e3;
        float mine = (k == 0) ? e0 : (k == 1) ? e1 : (k == 2) ? e2 : e3;
        sMix[hh * 4 + k] = (mine / s) * 1.4426950408889634f;
    }

    const int i0   = ib * 64;
    const int arow = tid >> 2;
    const int aq   = tid & 3;
    const __half* S4b = S4 + (size_t)b * KG * N_SEQ * N_SEQ;
    const long   PL  = (long)N_SEQ * N_SEQ;
    const size_t vbase0 = ((size_t)(b * HEFF + hg * 2 + 0)) * HD * N_SEQ;
    const size_t vbase1 = ((size_t)(b * HEFF + hg * 2 + 1)) * HD * N_SEQ;

    // issue cp.async copies for tile jt into stage + V parity buffer
    auto issue_tile = [&](int jt, int parity) {
        const int j0 = jt * 64;
        #pragma unroll
        for (int it = 0; it < 4; it++) {           // V: 1024 x 16B
            int idx = it * 256 + tid;
            int hh = idx >> 9;
            int r  = (idx >> 3) & 63;
            int q  = idx & 7;
            size_t so = (hh ? vbase1 : vbase0) + (size_t)r * N_SEQ + j0 + q * 8;
            cp_async16(sb + OFF_V + (uint32_t)(parity * 2 + hh) * PBY
                          + (uint32_t)(r * 72 + q * 8) * 2, &Vt[so]);
        }
        #pragma unroll
        for (int it = 0; it < 8; it++) {           // S4: 2048 x 16B
            int idx = it * 256 + tid;
            int p  = idx >> 9;
            int r  = (idx >> 3) & 63;
            int q  = idx & 7;
            const __half* g = S4b + (size_t)p * PL
                            + (long)(i0 + r) * N_SEQ + j0 + q * 8;
            cp_async16(sb + OFF_S + (uint32_t)((p * 64 + r) * 72 + q * 8) * 2, g);
        }
        cp_commit();
    };

    float acc[2][4][4];
    #pragma unroll
    for (int i = 0; i < 2; i++)
        #pragma unroll
        for (int j = 0; j < 4; j++)
            #pragma unroll
            for (int q = 0; q < 4; q++) acc[i][j][q] = 0.0f;

    issue_tile(0, 0);

    for (int t = 0; t < 16; t++) {
        cp_wait<0>();
        __syncthreads();   // stage(t), Vbuf(t&1) ready; prev MMA done (reads P/V)

        // ---- phase A: combine from smem stage + exp2, store P fp16 ---------
        {
            const float mx00 = sMix[0], mx01 = sMix[1], mx02 = sMix[2], mx03 = sMix[3];
            const float mx10 = sMix[4], mx11 = sMix[5], mx12 = sMix[6], mx13 = sMix[7];
            const __half* srow = sStage + arow * 72 + aq * 16;
            float s0 = 0.0f, s1 = 0.0f;
            #pragma unroll
            for (int c = 0; c < 4; c++) {
                __half2 a01  = *(const __half2*)(srow + c * 4);
                __half2 a23  = *(const __half2*)(srow + c * 4 + 2);
                __half2 p101 = *(const __half2*)(srow + 64 * 72 + c * 4);
                __half2 p123 = *(const __half2*)(srow + 64 * 72 + c * 4 + 2);
                __half2 p201 = *(const __half2*)(srow + 128 * 72 + c * 4);
                __half2 p223 = *(const __half2*)(srow + 128 * 72 + c * 4 + 2);
                __half2 p301 = *(const __half2*)(srow + 192 * 72 + c * 4);
                __half2 p323 = *(const __half2*)(srow + 192 * 72 + c * 4 + 2);
                float2 fa0 = __half22float2(a01),  fa1 = __half22float2(a23);
                float2 f10 = __half22float2(p101), f11 = __half22float2(p123);
                float2 f20 = __half22float2(p201), f21 = __half22float2(p223);
                float2 f30 = __half22float2(p301), f31 = __half22float2(p323);
                const uint32_t po = (uint32_t)(arow * 72 + aq * 16 + c * 4) * 2;
                #pragma unroll
                for (int hh = 0; hh < 2; hh++) {
                    float m0 = hh ? mx10 : mx00, m1 = hh ? mx11 : mx01;
                    float m2 = hh ? mx12 : mx02, m3 = hh ? mx13 : mx03;
                    float q0 = fast_exp2(fmaf(m3, f30.x, fmaf(m2, f20.x, fmaf(m1, f10.x, m0 * fa0.x))));
                    float q1 = fast_exp2(fmaf(m3, f30.y, fmaf(m2, f20.y, fmaf(m1, f10.y, m0 * fa0.y))));
                    float q2 = fast_exp2(fmaf(m3, f31.x, fmaf(m2, f21.x, fmaf(m1, f11.x, m0 * fa1.x))));
                    float q3 = fast_exp2(fmaf(m3, f31.y, fmaf(m2, f21.y, fmaf(m1, f11.y, m0 * fa1.y))));
                    if (hh) s1 += (q0 + q1) + (q2 + q3);
                    else    s0 += (q0 + q1) + (q2 + q3);
                    uint2 hv;
                    hv.x = pack_h2(q0, q1);
                    hv.y = pack_h2(q2, q3);
                    *(uint2*)(sm + OFF_P + hh * PBY + po) = hv;
                }
            }
            s0 += __shfl_xor_sync(0xffffffffu, s0, 1);
            s0 += __shfl_xor_sync(0xffffffffu, s0, 2);
            s1 += __shfl_xor_sync(0xffffffffu, s1, 1);
            s1 += __shfl_xor_sync(0xffffffffu, s1, 2);
            if (aq == 0) {
                sSum[arow]      += s0;
                sSum[64 + arow] += s1;
            }
        }
        __syncthreads();   // stage fully consumed; P visible

        // ---- prefetch next tile (overlaps MMA) -----------------------------
        if (t + 1 < 16) issue_tile(t + 1, (t + 1) & 1);

        // ---- MMA: both heads, 1-pass fp16 (P @ V[parity t]) ----------------
        #pragma unroll
        for (int hh = 0; hh < 2; hh++) {
            const uint32_t uP = sb + OFF_P + hh * PBY;
            const uint32_t uV = sb + OFF_V + (uint32_t)((t & 1) * 2 + hh) * PBY;
            #pragma unroll
            for (int ks = 0; ks < 4; ks++) {
                const int k0 = ks * 16;
                const uint32_t aoff = (uint32_t)((wr * 16 + a_r) * 72 + k0 + a_k) * 2;
                const uint32_t boff = (uint32_t)((wc * 32 + b_r) * 72 + k0 + b_k) * 2;
                uint32_t ah[4];
                ldsm_x4(ah[0], ah[1], ah[2], ah[3], uP + aoff);
                uint32_t bv[4][2];
                #pragma unroll
                for (int nb = 0; nb < 2; nb++)
                    ldsm_x4(bv[2*nb][0], bv[2*nb][1], bv[2*nb+1][0], bv[2*nb+1][1],
                            uV + boff + nb * 16 * 72 * 2);
                #pragma unroll
                for (int nf = 0; nf < 4; nf++)
                    mma16816h(acc[hh][nf], ah, bv[nf]);
            }
        }
    }
    __syncthreads();

    // ---- epilogue: normalize, write ctx fp16 -------------------------------
    const int qrow = lane >> 2;
    const int qcol = (lane & 3) << 1;
    #pragma unroll
    for (int hh = 0; hh < 2; hh++)
        #pragma unroll
        for (int half = 0; half < 2; half++) {
            int r = wr * 16 + half * 8 + qrow;
            float inv = 1.0f / sSum[hh * 64 + r];
            long obase = ((long)b * N_SEQ + i0 + r) * DIM + (hg * 2 + hh) * HD;
            #pragma unroll
            for (int nf = 0; nf < 4; nf++) {
                int n = wc * 32 + nf * 8 + qcol;
                *(uint32_t*)&ctx[obase + n] =
                    pack_h2(acc[hh][nf][half * 2 + 0] * inv,
                            acc[hh][nf][half * 2 + 1] * inv);
            }
        }
}

// ---------------------------------------------------------------------------
extern "C" void kernel_launch(void* const* d_in, const int* in_sizes, int n_in,
                              void* d_out, int out_size)
{
    const float* x      = (const float*)d_in[0];
    const float* W_qkv  = (const float*)d_in[1];
    const float* W_v    = (const float*)d_in[2];
    const float* W_proj = (const float*)d_in[3];
    const float* b_proj = (const float*)d_in[4];
    const float* mixl   = (const float*)d_in[5];
    float* out = (float*)d_out;

    __half *pYh, *pV16, *pc16, *pS4h, *pVt;
    cudaGetSymbolAddress((void**)&pYh,  g_Yh);
    cudaGetSymbolAddress((void**)&pV16, g_V16);
    cudaGetSymbolAddress((void**)&pc16, g_c16);
    cudaGetSymbolAddress((void**)&pS4h, g_S4h);
    cudaGetSymbolAddress((void**)&pVt,  g_Vt);

    static bool attrDone = false;
    if (!attrDone) {
        cudaFuncSetAttribute(attn_kernel,
                             cudaFuncAttributeMaxDynamicSharedMemorySize, ATTN_SMEM);
        attrDone = true;
    }

    dim3 blk(256);

    // 1) Yh = fp16( x @ W_qkv[0:512].T )
    gemm_f32_h16<<<dim3(4, 64, 1), blk>>>(x, W_qkv, pYh, DIM, DIM, DIM, 512);

    // 2) V16 = fp16( x @ W_v.T )
    gemm_f32_h16<<<dim3(6, 64, 1), blk>>>(x, W_v, pV16, DIM, DIM, DIM, DIM);

    // 2b) V16 -> per-head transposed Vt
    vconvert<<<dim3(16, 96, 1), blk>>>(pV16, pVt);

    // 3) S4h = fp16( 0.125 * q @ k.T )
    gemm_h16_h16<<<dim3(8, 8, B_SZ * KG), blk>>>(
        pYh, pYh + 256, pS4h, HD, 512, 512, N_SEQ, 0.125f,
        (long)N_SEQ * 512, 64, (long)N_SEQ * 512, 64, (long)N_SEQ * N_SEQ, KG);

    // 4) attention -> ctx fp16
    attn_kernel<<<dim3(16, 6, 8), blk, ATTN_SMEM>>>(pS4h, pVt, mixl, pc16);

    // 5) out = ctx16 @ W_proj.T + b_proj
    gemm_h16_f32<<<dim3(6, 64, 1), blk>>>(pc16, W_proj, out, b_proj,
                                          DIM, DIM, DIM, DIM);
}

// round 14
// speedup vs baseline: 2.1364x; 1.2382x over previous
#include <cuda_runtime.h>
#include <cuda_bf16.h>
#include <cuda_fp16.h>
#include <cstdint>

// ---------------------------------------------------------------------------
// FiSHAttention: B=8, N=1024, dim=p=768, HEAD_DIM=64, K_GLOBAL=4, H_eff=12
// Pure-fp16 tensor pipeline + dual-stream overlap:
//   cvt: x,Wq,Wv,Wp -> fp16 (once; bitwise same as in-GEMM cvt)
//   main stream : Wq cvt -> Y -> S4 -> Wp cvt ----\
//   side stream : Wv cvt -> V -> vconvert --------+--> attn -> proj
//   GEMMs: unified pure-fp16 1-pass HMMA, cp.async double-buffered.
//   attn: cp.async-pipelined S4 stage + double-buffered V (round-13 kernel).
// Error model (calibrated): out_err ~= 0.44*unit-rounding per fp16 operand;
// measured 5.2e-4, margin ~1.9x.
// ---------------------------------------------------------------------------

#define B_SZ   8
#define N_SEQ  1024
#define DIM    768
#define KG     4
#define HD     64
#define HEFF   12

__device__ __half g_x16[B_SZ * N_SEQ * DIM];
__device__ __half g_Wq16[512 * DIM];
__device__ __half g_Wv16[DIM * DIM];
__device__ __half g_Wp16[DIM * DIM];
__device__ __half g_Yh [B_SZ * N_SEQ * 512];
__device__ __half g_V16[B_SZ * N_SEQ * DIM];
__device__ __half g_c16[B_SZ * N_SEQ * DIM];
__device__ __half g_S4h[(size_t)B_SZ * KG * N_SEQ * N_SEQ];   // 64 MB
__device__ __half g_Vt [(size_t)B_SZ * HEFF * HD * N_SEQ];

// ------------------------------ helpers ------------------------------------
__device__ __forceinline__ uint32_t smem_u32(const void* p) {
    uint32_t a;
    asm("{ .reg .u64 t; cvta.to.shared.u64 t, %1; cvt.u32.u64 %0, t; }"
        : "=r"(a) : "l"(p));
    return a;
}
__device__ __forceinline__ void ldsm_x4(uint32_t& r0, uint32_t& r1,
                                        uint32_t& r2, uint32_t& r3, uint32_t addr) {
    asm volatile("ldmatrix.sync.aligned.m8n8.x4.shared.b16 {%0,%1,%2,%3}, [%4];"
        : "=r"(r0), "=r"(r1), "=r"(r2), "=r"(r3) : "r"(addr));
}
__device__ __forceinline__ void mma16816h(float* c, const uint32_t* a,
                                          const uint32_t* b) {
    asm volatile("mma.sync.aligned.m16n8k16.row.col.f32.f16.f16.f32 "
        "{%0,%1,%2,%3}, {%4,%5,%6,%7}, {%8,%9}, {%0,%1,%2,%3};"
        : "+f"(c[0]), "+f"(c[1]), "+f"(c[2]), "+f"(c[3])
        : "r"(a[0]), "r"(a[1]), "r"(a[2]), "r"(a[3]), "r"(b[0]), "r"(b[1]));
}
__device__ __forceinline__ void cp_async16(uint32_t s, const void* g) {
    asm volatile("cp.async.cg.shared.global [%0], [%1], 16;" :: "r"(s), "l"(g));
}
__device__ __forceinline__ void cp_commit() {
    asm volatile("cp.async.commit_group;" ::: "memory");
}
template<int N> __device__ __forceinline__ void cp_wait() {
    asm volatile("cp.async.wait_group %0;" :: "n"(N) : "memory");
}
__device__ __forceinline__ uint32_t pack_h2(float x, float y) {
    return ((uint32_t)__half_as_ushort(__float2half(y)) << 16)
         | __half_as_ushort(__float2half(x));
}

__device__ __forceinline__ float fast_exp(float x) {
    x = fmaxf(x, -80.0f);
    const float L2E = 1.4426950408889634f;
    float t  = fmaf(x, L2E, 12582912.0f);
    float nf = t - 12582912.0f;
    int   ni = __float_as_int(t) - 0x4B400000;
    float f  = fmaf(x, L2E, -nf);
    f = fmaf(x, 1.9259629911266175e-8f, f);
    float p;
    p = 1.33335581e-3f;
    p = fmaf(p, f, 9.61812910e-3f);
    p = fmaf(p, f, 5.55041087e-2f);
    p = fmaf(p, f, 2.40226507e-1f);
    p = fmaf(p, f, 6.93147181e-1f);
    p = fmaf(p, f, 1.0f);
    return __int_as_float(__float_as_int(p) + (ni << 23));
}
__device__ __forceinline__ float fast_exp2(float y) {
    y = fmaxf(y, -100.0f);
    float t  = y + 12582912.0f;
    float nf = t - 12582912.0f;
    int   ni = __float_as_int(t) - 0x4B400000;
    float f  = y - nf;
    float p;
    p = 1.33335581e-3f;
    p = fmaf(p, f, 9.61812910e-3f);
    p = fmaf(p, f, 5.55041087e-2f);
    p = fmaf(p, f, 2.40226507e-1f);
    p = fmaf(p, f, 6.93147181e-1f);
    p = fmaf(p, f, 1.0f);
    return __int_as_float(__float_as_int(p) + (ni << 23));
}

// ===========================================================================
// cvt16: f32 -> fp16 elementwise (float4-wide).
// ===========================================================================
__global__ __launch_bounds__(256) void cvt16(
    const float* __restrict__ in, __half* __restrict__ o, int n4)
{
    int i = blockIdx.x * 256 + threadIdx.x;
    if (i >= n4) return;
    float4 v = ((const float4*)in)[i];
    uint2 h;
    h.x = pack_h2(v.x, v.y);
    h.y = pack_h2(v.z, v.w);
    ((uint2*)o)[i] = h;
}

// ===========================================================================
// Unified pure-fp16 TN GEMM, cp.async 2-stage double-buffered.
// C = alpha * A @ B^T; out = f32 (+bias) if Cf, else fp16 (Ch). Batched.
// CTA 128x128, 8 warps (4x2), warp tile 32x64, BK=32. smem 40KB dyn.
// ===========================================================================
#define BKC  32
#define TSTR 40
#define GTB  (128 * TSTR * 2)      // 10240 B per operand tile
#define GSMEM (4 * GTB)            // 2 stages x 2 operands

__global__ __launch_bounds__(256) void gemm16(
    const __half* __restrict__ A, const __half* __restrict__ B,
    float* __restrict__ Cf, __half* __restrict__ Ch,
    const float* __restrict__ bias,
    int K, int lda, int ldb, int ldc, float alpha,
    long sAo, long sAi, long sBo, long sBi, long sC, int innerMod)
{
    {
        int z = blockIdx.z;
        int outer = z / innerMod;
        int inner = z - outer * innerMod;
        A += (long)outer * sAo + (long)inner * sAi;
        B += (long)outer * sBo + (long)inner * sBi;
        if (Cf) Cf += (long)z * sC;
        if (Ch) Ch += (long)z * sC;
    }
    const int row0 = blockIdx.y * 128;
    const int col0 = blockIdx.x * 128;

    extern __shared__ char dsm[];
    const uint32_t base = smem_u32(dsm);

    const int tid  = threadIdx.x;
    const int wid  = tid >> 5;
    const int lane = tid & 31;
    const int wm   = wid >> 1;
    const int wn   = wid & 1;
    const int a_r = lane & 15;
    const int a_k = (lane >> 4) << 3;
    const int b_r = (lane & 7) + ((lane >> 4) << 3);
    const int b_k = ((lane >> 3) & 1) << 3;

    float acc[2][8][4];
    #pragma unroll
    for (int i = 0; i < 2; i++)
        #pragma unroll
        for (int j = 0; j < 8; j++)
            #pragma unroll
            for (int q = 0; q < 4; q++) acc[i][j][q] = 0.0f;

    auto issue = [&](int t) {
        const uint32_t sb = base + (uint32_t)(t & 1) * (2 * GTB);
        #pragma unroll
        for (int it = 0; it < 2; it++) {
            int idx = it * 256 + tid;
            int r = idx >> 2, q = (idx & 3) << 3;
            cp_async16(sb + (uint32_t)(r * TSTR + q) * 2,
                       &A[(long)(row0 + r) * lda + t * BKC + q]);
        }
        #pragma unroll
        for (int it = 0; it < 2; it++) {
            int idx = it * 256 + tid;
            int r = idx >> 2, q = (idx & 3) << 3;
            cp_async16(sb + GTB + (uint32_t)(r * TSTR + q) * 2,
                       &B[(long)(col0 + r) * ldb + t * BKC + q]);
        }
        cp_commit();
    };

    const int nch = K / BKC;
    issue(0);

    for (int t = 0; t < nch; t++) {
        if (t + 1 < nch) {
            issue(t + 1);
            cp_wait<1>();
        } else {
            cp_wait<0>();
        }
        __syncthreads();

        const uint32_t uA = base + (uint32_t)(t & 1) * (2 * GTB);
        const uint32_t uB = uA + GTB;

        #pragma unroll
        for (int ks = 0; ks < 2; ks++) {
            const int k0 = ks * 16;
            const uint32_t aoff = (uint32_t)((wm * 32 + a_r) * TSTR + k0 + a_k) * 2;
            const uint32_t boff = (uint32_t)((wn * 64 + b_r) * TSTR + k0 + b_k) * 2;
            uint32_t af[2][4];
            ldsm_x4(af[0][0], af[0][1], af[0][2], af[0][3], uA + aoff);
            ldsm_x4(af[1][0], af[1][1], af[1][2], af[1][3], uA + aoff + 16 * TSTR * 2);
            uint32_t bv[8][2];
            #pragma unroll
            for (int nb = 0; nb < 4; nb++)
                ldsm_x4(bv[2*nb][0], bv[2*nb][1], bv[2*nb+1][0], bv[2*nb+1][1],
                        uB + boff + nb * 16 * TSTR * 2);
            #pragma unroll
            for (int mf = 0; mf < 2; mf++)
                #pragma unroll
                for (int nf = 0; nf < 8; nf++)
                    mma16816h(acc[mf][nf], af[mf], bv[nf]);
        }
        __syncthreads();
    }

    const int qrow = lane >> 2;
    const int qcol = (lane & 3) << 1;
    #pragma unroll
    for (int mf = 0; mf < 2; mf++)
        #pragma unroll
        for (int half = 0; half < 2; half++) {
            long r = row0 + wm * 32 + mf * 16 + half * 8 + qrow;
            #pragma unroll
            for (int nf = 0; nf < 8; nf++) {
                int n = col0 + wn * 64 + nf * 8 + qcol;
                float ox = alpha * acc[mf][nf][half * 2 + 0];
                float oy = alpha * acc[mf][nf][half * 2 + 1];
                if (Cf) {
                    float2 o;
                    o.x = ox; o.y = oy;
                    if (bias) { o.x += bias[n]; o.y += bias[n + 1]; }
                    *(float2*)&Cf[r * ldc + n] = o;
                } else {
                    *(uint32_t*)&Ch[r * ldc + n] = pack_h2(ox, oy);
                }
            }
        }
}

// ===========================================================================
// V transpose (fp16 in/out).
// ===========================================================================
__global__ __launch_bounds__(256) void vconvert(
    const __half* __restrict__ V, __half* __restrict__ Vt)
{
    const int j0   = blockIdx.x * 64;
    const int bhid = blockIdx.y;
    const int b    = bhid / HEFF;
    const int h    = bhid - b * HEFF;

    __shared__ __half sT[64][72];
    const int tid = threadIdx.x;

    #pragma unroll
    for (int it = 0; it < 4; it++) {
        int e = it * 256 + tid;
        int j = e >> 4, dq = (e & 15) << 2;
        uint2 u = *(const uint2*)&V[((long)b * N_SEQ + j0 + j) * DIM + h * HD + dq];
        __half2 a = *(__half2*)&u.x;
        __half2 c = *(__half2*)&u.y;
        sT[dq + 0][j] = __low2half(a);  sT[dq + 1][j] = __high2half(a);
        sT[dq + 2][j] = __low2half(c);  sT[dq + 3][j] = __high2half(c);
    }
    __syncthreads();

    const int d = tid >> 2, jseg = (tid & 3) << 4;
    size_t dst = ((size_t)bhid * HD + d) * N_SEQ + j0 + jseg;
    *(uint4*)&Vt[dst]     = *(uint4*)&sT[d][jseg];
    *(uint4*)&Vt[dst + 8] = *(uint4*)&sT[d][jseg + 8];
}

// ===========================================================================
// Attention (round-13 kernel, unchanged): cp.async pipelined, 2 heads/CTA.
// ===========================================================================
#define PBY 9216
#define OFF_V 0
#define OFF_P (4 * PBY)
#define OFF_S (6 * PBY)
#define OFF_SUM (OFF_S + 36864)
#define OFF_MIX (OFF_SUM + 512)
#define ATTN_SMEM (OFF_MIX + 64)

__global__ __launch_bounds__(256, 2) void attn_kernel(
    const __half* __restrict__ S4, const __half* __restrict__ Vt,
    const float* __restrict__ mixl, __half* __restrict__ ctx)
{
    const int ib = blockIdx.x;
    const int hg = blockIdx.y;
    const int b  = blockIdx.z;

    extern __shared__ char sm[];
    const uint32_t sb = smem_u32(sm);
    float* sSum = (float*)(sm + OFF_SUM);
    float* sMix = (float*)(sm + OFF_MIX);
    const __half* sStage = (const __half*)(sm + OFF_S);

    const int tid  = threadIdx.x;
    const int wid  = tid >> 5;
    const int lane = tid & 31;
    const int wr   = wid >> 1;
    const int wc   = wid & 1;
    const int a_r  = lane & 15;
    const int a_k  = (lane >> 4) << 3;
    const int b_r  = (lane & 7) + ((lane >> 4) << 3);
    const int b_k  = ((lane >> 3) & 1) << 3;

    if (tid < 128) sSum[tid] = 0.0f;
    if (tid < 8) {
        int hh = tid >> 2, k = tid & 3;
        const float* ml = mixl + (hg * 2 + hh) * 4;
        float l0 = ml[0], l1 = ml[1], l2 = ml[2], l3 = ml[3];
        float m  = fmaxf(fmaxf(l0, l1), fmaxf(l2, l3));
        float e0 = fast_exp(l0 - m), e1 = fast_exp(l1 - m);
        float e2 = fast_exp(l2 - m), e3 = fast_exp(l3 - m);
        float s  = e0 + e1 + e2 + e3;
        float mine = (k == 0) ? e0 : (k == 1) ? e1 : (k == 2) ? e2 : e3;
        sMix[hh * 4 + k] = (mine / s) * 1.4426950408889634f;
    }

    const int i0   = ib * 64;
    const int arow = tid >> 2;
    const int aq   = tid & 3;
    const __half* S4b = S4 + (size_t)b * KG * N_SEQ * N_SEQ;
    const long   PL  = (long)N_SEQ * N_SEQ;
    const size_t vbase0 = ((size_t)(b * HEFF + hg * 2 + 0)) * HD * N_SEQ;
    const size_t vbase1 = ((size_t)(b * HEFF + hg * 2 + 1)) * HD * N_SEQ;

    auto issue_tile = [&](int jt, int parity) {
        const int j0 = jt * 64;
        #pragma unroll
        for (int it = 0; it < 4; it++) {
            int idx = it * 256 + tid;
            int hh = idx >> 9;
            int r  = (idx >> 3) & 63;
            int q  = idx & 7;
            size_t so = (hh ? vbase1 : vbase0) + (size_t)r * N_SEQ + j0 + q * 8;
            cp_async16(sb + OFF_V + (uint32_t)(parity * 2 + hh) * PBY
                          + (uint32_t)(r * 72 + q * 8) * 2, &Vt[so]);
        }
        #pragma unroll
        for (int it = 0; it < 8; it++) {
            int idx = it * 256 + tid;
            int p  = idx >> 9;
            int r  = (idx >> 3) & 63;
            int q  = idx & 7;
            const __half* g = S4b + (size_t)p * PL
                            + (long)(i0 + r) * N_SEQ + j0 + q * 8;
            cp_async16(sb + OFF_S + (uint32_t)((p * 64 + r) * 72 + q * 8) * 2, g);
        }
        cp_commit();
    };

    float acc[2][4][4];
    #pragma unroll
    for (int i = 0; i < 2; i++)
        #pragma unroll
        for (int j = 0; j < 4; j++)
            #pragma unroll
            for (int q = 0; q < 4; q++) acc[i][j][q] = 0.0f;

    issue_tile(0, 0);

    for (int t = 0; t < 16; t++) {
        cp_wait<0>();
        __syncthreads();

        {
            const float mx00 = sMix[0], mx01 = sMix[1], mx02 = sMix[2], mx03 = sMix[3];
            const float mx10 = sMix[4], mx11 = sMix[5], mx12 = sMix[6], mx13 = sMix[7];
            const __half* srow = sStage + arow * 72 + aq * 16;
            float s0 = 0.0f, s1 = 0.0f;
            #pragma unroll
            for (int c = 0; c < 4; c++) {
                __half2 a01  = *(const __half2*)(srow + c * 4);
                __half2 a23  = *(const __half2*)(srow + c * 4 + 2);
                __half2 p101 = *(const __half2*)(srow + 64 * 72 + c * 4);
                __half2 p123 = *(const __half2*)(srow + 64 * 72 + c * 4 + 2);
                __half2 p201 = *(const __half2*)(srow + 128 * 72 + c * 4);
                __half2 p223 = *(const __half2*)(srow + 128 * 72 + c * 4 + 2);
                __half2 p301 = *(const __half2*)(srow + 192 * 72 + c * 4);
                __half2 p323 = *(const __half2*)(srow + 192 * 72 + c * 4 + 2);
                float2 fa0 = __half22float2(a01),  fa1 = __half22float2(a23);
                float2 f10 = __half22float2(p101), f11 = __half22float2(p123);
                float2 f20 = __half22float2(p201), f21 = __half22float2(p223);
                float2 f30 = __half22float2(p301), f31 = __half22float2(p323);
                const uint32_t po = (uint32_t)(arow * 72 + aq * 16 + c * 4) * 2;
                #pragma unroll
                for (int hh = 0; hh < 2; hh++) {
                    float m0 = hh ? mx10 : mx00, m1 = hh ? mx11 : mx01;
                    float m2 = hh ? mx12 : mx02, m3 = hh ? mx13 : mx03;
                    float q0 = fast_exp2(fmaf(m3, f30.x, fmaf(m2, f20.x, fmaf(m1, f10.x, m0 * fa0.x))));
                    float q1 = fast_exp2(fmaf(m3, f30.y, fmaf(m2, f20.y, fmaf(m1, f10.y, m0 * fa0.y))));
                    float q2 = fast_exp2(fmaf(m3, f31.x, fmaf(m2, f21.x, fmaf(m1, f11.x, m0 * fa1.x))));
                    float q3 = fast_exp2(fmaf(m3, f31.y, fmaf(m2, f21.y, fmaf(m1, f11.y, m0 * fa1.y))));
                    if (hh) s1 += (q0 + q1) + (q2 + q3);
                    else    s0 += (q0 + q1) + (q2 + q3);
                    uint2 hv;
                    hv.x = pack_h2(q0, q1);
                    hv.y = pack_h2(q2, q3);
                    *(uint2*)(sm + OFF_P + hh * PBY + po) = hv;
                }
            }
            s0 += __shfl_xor_sync(0xffffffffu, s0, 1);
            s0 += __shfl_xor_sync(0xffffffffu, s0, 2);
            s1 += __shfl_xor_sync(0xffffffffu, s1, 1);
            s1 += __shfl_xor_sync(0xffffffffu, s1, 2);
            if (aq == 0) {
                sSum[arow]      += s0;
                sSum[64 + arow] += s1;
            }
        }
        __syncthreads();

        if (t + 1 < 16) issue_tile(t + 1, (t + 1) & 1);

        #pragma unroll
        for (int hh = 0; hh < 2; hh++) {
            const uint32_t uP = sb + OFF_P + hh * PBY;
            const uint32_t uV = sb + OFF_V + (uint32_t)((t & 1) * 2 + hh) * PBY;
            #pragma unroll
            for (int ks = 0; ks < 4; ks++) {
                const int k0 = ks * 16;
                const uint32_t aoff = (uint32_t)((wr * 16 + a_r) * 72 + k0 + a_k) * 2;
                const uint32_t boff = (uint32_t)((wc * 32 + b_r) * 72 + k0 + b_k) * 2;
                uint32_t ah[4];
                ldsm_x4(ah[0], ah[1], ah[2], ah[3], uP + aoff);
                uint32_t bv[4][2];
                #pragma unroll
                for (int nb = 0; nb < 2; nb++)
                    ldsm_x4(bv[2*nb][0], bv[2*nb][1], bv[2*nb+1][0], bv[2*nb+1][1],
                            uV + boff + nb * 16 * 72 * 2);
                #pragma unroll
                for (int nf = 0; nf < 4; nf++)
                    mma16816h(acc[hh][nf], ah, bv[nf]);
            }
        }
    }
    __syncthreads();

    const int qrow = lane >> 2;
    const int qcol = (lane & 3) << 1;
    #pragma unroll
    for (int hh = 0; hh < 2; hh++)
        #pragma unroll
        for (int half = 0; half < 2; half++) {
            int r = wr * 16 + half * 8 + qrow;
            float inv = 1.0f / sSum[hh * 64 + r];
            long obase = ((long)b * N_SEQ + i0 + r) * DIM + (hg * 2 + hh) * HD;
            #pragma unroll
            for (int nf = 0; nf < 4; nf++) {
                int n = wc * 32 + nf * 8 + qcol;
                *(uint32_t*)&ctx[obase + n] =
                    pack_h2(acc[hh][nf][half * 2 + 0] * inv,
                            acc[hh][nf][half * 2 + 1] * inv);
            }
        }
}

// ---------------------------------------------------------------------------
extern "C" void kernel_launch(void* const* d_in, const int* in_sizes, int n_in,
                              void* d_out, int out_size)
{
    const float* x      = (const float*)d_in[0];
    const float* W_qkv  = (const float*)d_in[1];
    const float* W_v    = (const float*)d_in[2];
    const float* W_proj = (const float*)d_in[3];
    const float* b_proj = (const float*)d_in[4];
    const float* mixl   = (const float*)d_in[5];
    float* out = (float*)d_out;

    __half *px16, *pWq, *pWv, *pWp, *pYh, *pV16, *pc16, *pS4h, *pVt;
    cudaGetSymbolAddress((void**)&px16, g_x16);
    cudaGetSymbolAddress((void**)&pWq,  g_Wq16);
    cudaGetSymbolAddress((void**)&pWv,  g_Wv16);
    cudaGetSymbolAddress((void**)&pWp,  g_Wp16);
    cudaGetSymbolAddress((void**)&pYh,  g_Yh);
    cudaGetSymbolAddress((void**)&pV16, g_V16);
    cudaGetSymbolAddress((void**)&pc16, g_c16);
    cudaGetSymbolAddress((void**)&pS4h, g_S4h);
    cudaGetSymbolAddress((void**)&pVt,  g_Vt);

    static cudaStream_t s1 = nullptr;
    static cudaEvent_t evX = nullptr, evJ = nullptr;
    static bool attrDone = false;
    if (!attrDone) {
        cudaFuncSetAttribute(attn_kernel,
                             cudaFuncAttributeMaxDynamicSharedMemorySize, ATTN_SMEM);
        cudaStreamCreateWithFlags(&s1, cudaStreamNonBlocking);
        cudaEventCreateWithFlags(&evX, cudaEventDisableTiming);
        cudaEventCreateWithFlags(&evJ, cudaEventDisableTiming);
        attrDone = true;
    }

    dim3 blk(256);
    const int NX4 = B_SZ * N_SEQ * DIM / 4;   // 1572864
    const int NW4 = DIM * DIM / 4;            // 147456
    const int NQ4 = 512 * DIM / 4;            // 98304

    // ---- main: x -> fp16, then fork ---------------------------------------
    cvt16<<<(NX4 + 255) / 256, blk>>>(x, px16, NX4);
    cudaEventRecord(evX, 0);
    cudaStreamWaitEvent(s1, evX, 0);

    // ---- side stream: Wv cvt -> V -> vconvert -----------------------------
    cvt16<<<(NW4 + 255) / 256, blk, 0, s1>>>(W_v, pWv, NW4);
    gemm16<<<dim3(6, 64, 1), blk, GSMEM, s1>>>(
        px16, pWv, nullptr, pV16, nullptr, DIM, DIM, DIM, DIM, 1.0f,
        0, 0, 0, 0, 0, 1);
    vconvert<<<dim3(16, 96, 1), blk, 0, s1>>>(pV16, pVt);
    cudaEventRecord(evJ, s1);

    // ---- main: Wq cvt -> Y -> S4 -> Wp cvt --------------------------------
    cvt16<<<(NQ4 + 255) / 256, blk>>>(W_qkv, pWq, NQ4);
    gemm16<<<dim3(4, 64, 1), blk, GSMEM>>>(
        px16, pWq, nullptr, pYh, nullptr, DIM, DIM, DIM, 512, 1.0f,
        0, 0, 0, 0, 0, 1);
    gemm16<<<dim3(8, 8, B_SZ * KG), blk, GSMEM>>>(
        pYh, pYh + 256, nullptr, pS4h, nullptr, HD, 512, 512, N_SEQ, 0.125f,
        (long)N_SEQ * 512, 64, (long)N_SEQ * 512, 64, (long)N_SEQ * N_SEQ, KG);
    cvt16<<<(NW4 + 255) / 256, blk>>>(W_proj, pWp, NW4);

    // ---- join, then attn + proj on main -----------------------------------
    cudaStreamWaitEvent(0, evJ, 0);
    attn_kernel<<<dim3(16, 6, 8), blk, ATTN_SMEM>>>(pS4h, pVt, mixl, pc16);
    gemm16<<<dim3(6, 64, 1), blk, GSMEM>>>(
        pc16, pWp, out, nullptr, b_proj, DIM, DIM, DIM, DIM, 1.0f,
        0, 0, 0, 0, 0, 1);
}

// round 15
// speedup vs baseline: 2.1763x; 1.0186x over previous
#include <cuda_runtime.h>
#include <cuda_bf16.h>
#include <cuda_fp16.h>
#include <cstdint>

// ---------------------------------------------------------------------------
// FiSHAttention: B=8, N=1024, dim=p=768, HEAD_DIM=64, K_GLOBAL=4, H_eff=12
// Pure-fp16 tensor pipeline + dual-stream overlap + MUFU exp:
//   cvt: x,Wq,Wv,Wp -> fp16 (once)
//   main stream : Wq cvt -> Y -> S4 -> Wp cvt ----\
//   side stream : Wv cvt -> V -> vconvert --------+--> attn -> proj
//   GEMMs: unified pure-fp16 1-pass HMMA, cp.async double-buffered.
//   attn: cp.async-pipelined; exp via MUFU ex2.approx (idle pipe, ~25us for
//         100M exps at 4T/s chip) instead of ~8 FMA-pipe ops each.
// Error model (calibrated): out_err ~= 0.44*unit-rounding per fp16 operand;
// measured 5.2e-4, margin ~1.9x. ex2.approx (~2 ulp) is more accurate than
// the poly it replaces.
// ---------------------------------------------------------------------------

#define B_SZ   8
#define N_SEQ  1024
#define DIM    768
#define KG     4
#define HD     64
#define HEFF   12

__device__ __half g_x16[B_SZ * N_SEQ * DIM];
__device__ __half g_Wq16[512 * DIM];
__device__ __half g_Wv16[DIM * DIM];
__device__ __half g_Wp16[DIM * DIM];
__device__ __half g_Yh [B_SZ * N_SEQ * 512];
__device__ __half g_V16[B_SZ * N_SEQ * DIM];
__device__ __half g_c16[B_SZ * N_SEQ * DIM];
__device__ __half g_S4h[(size_t)B_SZ * KG * N_SEQ * N_SEQ];   // 64 MB
__device__ __half g_Vt [(size_t)B_SZ * HEFF * HD * N_SEQ];

// ------------------------------ helpers ------------------------------------
__device__ __forceinline__ uint32_t smem_u32(const void* p) {
    uint32_t a;
    asm("{ .reg .u64 t; cvta.to.shared.u64 t, %1; cvt.u32.u64 %0, t; }"
        : "=r"(a) : "l"(p));
    return a;
}
__device__ __forceinline__ void ldsm_x4(uint32_t& r0, uint32_t& r1,
                                        uint32_t& r2, uint32_t& r3, uint32_t addr) {
    asm volatile("ldmatrix.sync.aligned.m8n8.x4.shared.b16 {%0,%1,%2,%3}, [%4];"
        : "=r"(r0), "=r"(r1), "=r"(r2), "=r"(r3) : "r"(addr));
}
__device__ __forceinline__ void mma16816h(float* c, const uint32_t* a,
                                          const uint32_t* b) {
    asm volatile("mma.sync.aligned.m16n8k16.row.col.f32.f16.f16.f32 "
        "{%0,%1,%2,%3}, {%4,%5,%6,%7}, {%8,%9}, {%0,%1,%2,%3};"
        : "+f"(c[0]), "+f"(c[1]), "+f"(c[2]), "+f"(c[3])
        : "r"(a[0]), "r"(a[1]), "r"(a[2]), "r"(a[3]), "r"(b[0]), "r"(b[1]));
}
__device__ __forceinline__ void cp_async16(uint32_t s, const void* g) {
    asm volatile("cp.async.cg.shared.global [%0], [%1], 16;" :: "r"(s), "l"(g));
}
__device__ __forceinline__ void cp_commit() {
    asm volatile("cp.async.commit_group;" ::: "memory");
}
template<int N> __device__ __forceinline__ void cp_wait() {
    asm volatile("cp.async.wait_group %0;" :: "n"(N) : "memory");
}
__device__ __forceinline__ uint32_t pack_h2(float x, float y) {
    return ((uint32_t)__half_as_ushort(__float2half(y)) << 16)
         | __half_as_ushort(__float2half(x));
}
// MUFU-based 2^y (ex2.approx, ~2 ulp). MUFU pipe is otherwise idle here.
__device__ __forceinline__ float mufu_exp2(float y) {
    float r;
    asm("ex2.approx.f32 %0, %1;" : "=f"(r) : "f"(y));
    return r;
}

#define BKC  32
#define TSTR 40
#define GTB  (128 * TSTR * 2)
#define GSMEM (4 * GTB)

// ===========================================================================
// cvt16: f32 -> fp16 elementwise.
// ===========================================================================
__global__ __launch_bounds__(256) void cvt16(
    const float* __restrict__ in, __half* __restrict__ o, int n4)
{
    int i = blockIdx.x * 256 + threadIdx.x;
    if (i >= n4) return;
    float4 v = ((const float4*)in)[i];
    uint2 h;
    h.x = pack_h2(v.x, v.y);
    h.y = pack_h2(v.z, v.w);
    ((uint2*)o)[i] = h;
}

// ===========================================================================
// Unified pure-fp16 TN GEMM, cp.async 2-stage double-buffered.
// ===========================================================================
__global__ __launch_bounds__(256) void gemm16(
    const __half* __restrict__ A, const __half* __restrict__ B,
    float* __restrict__ Cf, __half* __restrict__ Ch,
    const float* __restrict__ bias,
    int K, int lda, int ldb, int ldc, float alpha,
    long sAo, long sAi, long sBo, long sBi, long sC, int innerMod)
{
    {
        int z = blockIdx.z;
        int outer = z / innerMod;
        int inner = z - outer * innerMod;
        A += (long)outer * sAo + (long)inner * sAi;
        B += (long)outer * sBo + (long)inner * sBi;
        if (Cf) Cf += (long)z * sC;
        if (Ch) Ch += (long)z * sC;
    }
    const int row0 = blockIdx.y * 128;
    const int col0 = blockIdx.x * 128;

    extern __shared__ char dsm[];
    const uint32_t base = smem_u32(dsm);

    const int tid  = threadIdx.x;
    const int wid  = tid >> 5;
    const int lane = tid & 31;
    const int wm   = wid >> 1;
    const int wn   = wid & 1;
    const int a_r = lane & 15;
    const int a_k = (lane >> 4) << 3;
    const int b_r = (lane & 7) + ((lane >> 4) << 3);
    const int b_k = ((lane >> 3) & 1) << 3;

    float acc[2][8][4];
    #pragma unroll
    for (int i = 0; i < 2; i++)
        #pragma unroll
        for (int j = 0; j < 8; j++)
            #pragma unroll
            for (int q = 0; q < 4; q++) acc[i][j][q] = 0.0f;

    auto issue = [&](int t) {
        const uint32_t sb = base + (uint32_t)(t & 1) * (2 * GTB);
        #pragma unroll
        for (int it = 0; it < 2; it++) {
            int idx = it * 256 + tid;
            int r = idx >> 2, q = (idx & 3) << 3;
            cp_async16(sb + (uint32_t)(r * TSTR + q) * 2,
                       &A[(long)(row0 + r) * lda + t * BKC + q]);
        }
        #pragma unroll
        for (int it = 0; it < 2; it++) {
            int idx = it * 256 + tid;
            int r = idx >> 2, q = (idx & 3) << 3;
            cp_async16(sb + GTB + (uint32_t)(r * TSTR + q) * 2,
                       &B[(long)(col0 + r) * ldb + t * BKC + q]);
        }
        cp_commit();
    };

    const int nch = K / BKC;
    issue(0);

    for (int t = 0; t < nch; t++) {
        if (t + 1 < nch) {
            issue(t + 1);
            cp_wait<1>();
        } else {
            cp_wait<0>();
        }
        __syncthreads();

        const uint32_t uA = base + (uint32_t)(t & 1) * (2 * GTB);
        const uint32_t uB = uA + GTB;

        #pragma unroll
        for (int ks = 0; ks < 2; ks++) {
            const int k0 = ks * 16;
            const uint32_t aoff = (uint32_t)((wm * 32 + a_r) * TSTR + k0 + a_k) * 2;
            const uint32_t boff = (uint32_t)((wn * 64 + b_r) * TSTR + k0 + b_k) * 2;
            uint32_t af[2][4];
            ldsm_x4(af[0][0], af[0][1], af[0][2], af[0][3], uA + aoff);
            ldsm_x4(af[1][0], af[1][1], af[1][2], af[1][3], uA + aoff + 16 * TSTR * 2);
            uint32_t bv[8][2];
            #pragma unroll
            for (int nb = 0; nb < 4; nb++)
                ldsm_x4(bv[2*nb][0], bv[2*nb][1], bv[2*nb+1][0], bv[2*nb+1][1],
                        uB + boff + nb * 16 * TSTR * 2);
            #pragma unroll
            for (int mf = 0; mf < 2; mf++)
                #pragma unroll
                for (int nf = 0; nf < 8; nf++)
                    mma16816h(acc[mf][nf], af[mf], bv[nf]);
        }
        __syncthreads();
    }

    const int qrow = lane >> 2;
    const int qcol = (lane & 3) << 1;
    #pragma unroll
    for (int mf = 0; mf < 2; mf++)
        #pragma unroll
        for (int half = 0; half < 2; half++) {
            long r = row0 + wm * 32 + mf * 16 + half * 8 + qrow;
            #pragma unroll
            for (int nf = 0; nf < 8; nf++) {
                int n = col0 + wn * 64 + nf * 8 + qcol;
                float ox = alpha * acc[mf][nf][half * 2 + 0];
                float oy = alpha * acc[mf][nf][half * 2 + 1];
                if (Cf) {
                    float2 o;
                    o.x = ox; o.y = oy;
                    if (bias) { o.x += bias[n]; o.y += bias[n + 1]; }
                    *(float2*)&Cf[r * ldc + n] = o;
                } else {
                    *(uint32_t*)&Ch[r * ldc + n] = pack_h2(ox, oy);
                }
            }
        }
}

// ===========================================================================
// V transpose (fp16 in/out).
// ===========================================================================
__global__ __launch_bounds__(256) void vconvert(
    const __half* __restrict__ V, __half* __restrict__ Vt)
{
    const int j0   = blockIdx.x * 64;
    const int bhid = blockIdx.y;
    const int b    = bhid / HEFF;
    const int h    = bhid - b * HEFF;

    __shared__ __half sT[64][72];
    const int tid = threadIdx.x;

    #pragma unroll
    for (int it = 0; it < 4; it++) {
        int e = it * 256 + tid;
        int j = e >> 4, dq = (e & 15) << 2;
        uint2 u = *(const uint2*)&V[((long)b * N_SEQ + j0 + j) * DIM + h * HD + dq];
        __half2 a = *(__half2*)&u.x;
        __half2 c = *(__half2*)&u.y;
        sT[dq + 0][j] = __low2half(a);  sT[dq + 1][j] = __high2half(a);
        sT[dq + 2][j] = __low2half(c);  sT[dq + 3][j] = __high2half(c);
    }
    __syncthreads();

    const int d = tid >> 2, jseg = (tid & 3) << 4;
    size_t dst = ((size_t)bhid * HD + d) * N_SEQ + j0 + jseg;
    *(uint4*)&Vt[dst]     = *(uint4*)&sT[d][jseg];
    *(uint4*)&Vt[dst + 8] = *(uint4*)&sT[d][jseg + 8];
}

// ===========================================================================
// Attention: cp.async pipelined, 2 heads/CTA, MUFU exp. Grid (16, 6, 8).
// ===========================================================================
#define PBY 9216
#define OFF_V 0
#define OFF_P (4 * PBY)
#define OFF_S (6 * PBY)
#define OFF_SUM (OFF_S + 36864)
#define OFF_MIX (OFF_SUM + 512)
#define ATTN_SMEM (OFF_MIX + 64)

__global__ __launch_bounds__(256, 2) void attn_kernel(
    const __half* __restrict__ S4, const __half* __restrict__ Vt,
    const float* __restrict__ mixl, __half* __restrict__ ctx)
{
    const int ib = blockIdx.x;
    const int hg = blockIdx.y;
    const int b  = blockIdx.z;

    extern __shared__ char sm[];
    const uint32_t sb = smem_u32(sm);
    float* sSum = (float*)(sm + OFF_SUM);
    float* sMix = (float*)(sm + OFF_MIX);
    const __half* sStage = (const __half*)(sm + OFF_S);

    const int tid  = threadIdx.x;
    const int wid  = tid >> 5;
    const int lane = tid & 31;
    const int wr   = wid >> 1;
    const int wc   = wid & 1;
    const int a_r  = lane & 15;
    const int a_k  = (lane >> 4) << 3;
    const int b_r  = (lane & 7) + ((lane >> 4) << 3);
    const int b_k  = ((lane >> 3) & 1) << 3;

    if (tid < 128) sSum[tid] = 0.0f;
    if (tid < 8) {
        int hh = tid >> 2, k = tid & 3;
        const float* ml = mixl + (hg * 2 + hh) * 4;
        float l0 = ml[0], l1 = ml[1], l2 = ml[2], l3 = ml[3];
        const float L2E = 1.4426950408889634f;
        float m  = fmaxf(fmaxf(l0, l1), fmaxf(l2, l3));
        float e0 = mufu_exp2((l0 - m) * L2E), e1 = mufu_exp2((l1 - m) * L2E);
        float e2 = mufu_exp2((l2 - m) * L2E), e3 = mufu_exp2((l3 - m) * L2E);
        float s  = e0 + e1 + e2 + e3;
        float mine = (k == 0) ? e0 : (k == 1) ? e1 : (k == 2) ? e2 : e3;
        sMix[hh * 4 + k] = (mine / s) * L2E;
    }

    const int i0   = ib * 64;
    const int arow = tid >> 2;
    const int aq   = tid & 3;
    const __half* S4b = S4 + (size_t)b * KG * N_SEQ * N_SEQ;
    const long   PL  = (long)N_SEQ * N_SEQ;
    const size_t vbase0 = ((size_t)(b * HEFF + hg * 2 + 0)) * HD * N_SEQ;
    const size_t vbase1 = ((size_t)(b * HEFF + hg * 2 + 1)) * HD * N_SEQ;

    auto issue_tile = [&](int jt, int parity) {
        const int j0 = jt * 64;
        #pragma unroll
        for (int it = 0; it < 4; it++) {
            int idx = it * 256 + tid;
            int hh = idx >> 9;
            int r  = (idx >> 3) & 63;
            int q  = idx & 7;
            size_t so = (hh ? vbase1 : vbase0) + (size_t)r * N_SEQ + j0 + q * 8;
            cp_async16(sb + OFF_V + (uint32_t)(parity * 2 + hh) * PBY
                          + (uint32_t)(r * 72 + q * 8) * 2, &Vt[so]);
        }
        #pragma unroll
        for (int it = 0; it < 8; it++) {
            int idx = it * 256 + tid;
            int p  = idx >> 9;
            int r  = (idx >> 3) & 63;
            int q  = idx & 7;
            const __half* g = S4b + (size_t)p * PL
                            + (long)(i0 + r) * N_SEQ + j0 + q * 8;
            cp_async16(sb + OFF_S + (uint32_t)((p * 64 + r) * 72 + q * 8) * 2, g);
        }
        cp_commit();
    };

    float acc[2][4][4];
    #pragma unroll
    for (int i = 0; i < 2; i++)
        #pragma unroll
        for (int j = 0; j < 4; j++)
            #pragma unroll
            for (int q = 0; q < 4; q++) acc[i][j][q] = 0.0f;

    issue_tile(0, 0);

    for (int t = 0; t < 16; t++) {
        cp_wait<0>();
        __syncthreads();

        // ---- phase A: combine (FMA pipe) + MUFU exp2, store P fp16 ---------
        {
            const float mx00 = sMix[0], mx01 = sMix[1], mx02 = sMix[2], mx03 = sMix[3];
            const float mx10 = sMix[4], mx11 = sMix[5], mx12 = sMix[6], mx13 = sMix[7];
            const __half* srow = sStage + arow * 72 + aq * 16;
            float s0 = 0.0f, s1 = 0.0f;
            #pragma unroll
            for (int c = 0; c < 4; c++) {
                __half2 a01  = *(const __half2*)(srow + c * 4);
                __half2 a23  = *(const __half2*)(srow + c * 4 + 2);
                __half2 p101 = *(const __half2*)(srow + 64 * 72 + c * 4);
                __half2 p123 = *(const __half2*)(srow + 64 * 72 + c * 4 + 2);
                __half2 p201 = *(const __half2*)(srow + 128 * 72 + c * 4);
                __half2 p223 = *(const __half2*)(srow + 128 * 72 + c * 4 + 2);
                __half2 p301 = *(const __half2*)(srow + 192 * 72 + c * 4);
                __half2 p323 = *(const __half2*)(srow + 192 * 72 + c * 4 + 2);
                float2 fa0 = __half22float2(a01),  fa1 = __half22float2(a23);
                float2 f10 = __half22float2(p101), f11 = __half22float2(p123);
                float2 f20 = __half22float2(p201), f21 = __half22float2(p223);
                float2 f30 = __half22float2(p301), f31 = __half22float2(p323);
                const uint32_t po = (uint32_t)(arow * 72 + aq * 16 + c * 4) * 2;
                #pragma unroll
                for (int hh = 0; hh < 2; hh++) {
                    float m0 = hh ? mx10 : mx00, m1 = hh ? mx11 : mx01;
                    float m2 = hh ? mx12 : mx02, m3 = hh ? mx13 : mx03;
                    float q0 = mufu_exp2(fmaf(m3, f30.x, fmaf(m2, f20.x, fmaf(m1, f10.x, m0 * fa0.x))));
                    float q1 = mufu_exp2(fmaf(m3, f30.y, fmaf(m2, f20.y, fmaf(m1, f10.y, m0 * fa0.y))));
                    float q2 = mufu_exp2(fmaf(m3, f31.x, fmaf(m2, f21.x, fmaf(m1, f11.x, m0 * fa1.x))));
                    float q3 = mufu_exp2(fmaf(m3, f31.y, fmaf(m2, f21.y, fmaf(m1, f11.y, m0 * fa1.y))));
                    if (hh) s1 += (q0 + q1) + (q2 + q3);
                    else    s0 += (q0 + q1) + (q2 + q3);
                    uint2 hv;
                    hv.x = pack_h2(q0, q1);
                    hv.y = pack_h2(q2, q3);
                    *(uint2*)(sm + OFF_P + hh * PBY + po) = hv;
                }
            }
            s0 += __shfl_xor_sync(0xffffffffu, s0, 1);
            s0 += __shfl_xor_sync(0xffffffffu, s0, 2);
            s1 += __shfl_xor_sync(0xffffffffu, s1, 1);
            s1 += __shfl_xor_sync(0xffffffffu, s1, 2);
            if (aq == 0) {
                sSum[arow]      += s0;
                sSum[64 + arow] += s1;
            }
        }
        __syncthreads();

        if (t + 1 < 16) issue_tile(t + 1, (t + 1) & 1);

        // ---- MMA: both heads, 1-pass fp16 (P @ V[parity t]) ----------------
        #pragma unroll
        for (int hh = 0; hh < 2; hh++) {
            const uint32_t uP = sb + OFF_P + hh * PBY;
            const uint32_t uV = sb + OFF_V + (uint32_t)((t & 1) * 2 + hh) * PBY;
            #pragma unroll
            for (int ks = 0; ks < 4; ks++) {
                const int k0 = ks * 16;
                const uint32_t aoff = (uint32_t)((wr * 16 + a_r) * 72 + k0 + a_k) * 2;
                const uint32_t boff = (uint32_t)((wc * 32 + b_r) * 72 + k0 + b_k) * 2;
                uint32_t ah[4];
                ldsm_x4(ah[0], ah[1], ah[2], ah[3], uP + aoff);
                uint32_t bv[4][2];
                #pragma unroll
                for (int nb = 0; nb < 2; nb++)
                    ldsm_x4(bv[2*nb][0], bv[2*nb][1], bv[2*nb+1][0], bv[2*nb+1][1],
                            uV + boff + nb * 16 * 72 * 2);
                #pragma unroll
                for (int nf = 0; nf < 4; nf++)
                    mma16816h(acc[hh][nf], ah, bv[nf]);
            }
        }
    }
    __syncthreads();

    const int qrow = lane >> 2;
    const int qcol = (lane & 3) << 1;
    #pragma unroll
    for (int hh = 0; hh < 2; hh++)
        #pragma unroll
        for (int half = 0; half < 2; half++) {
            int r = wr * 16 + half * 8 + qrow;
            float inv = 1.0f / sSum[hh * 64 + r];
            long obase = ((long)b * N_SEQ + i0 + r) * DIM + (hg * 2 + hh) * HD;
            #pragma unroll
            for (int nf = 0; nf < 4; nf++) {
                int n = wc * 32 + nf * 8 + qcol;
                *(uint32_t*)&ctx[obase + n] =
                    pack_h2(acc[hh][nf][half * 2 + 0] * inv,
                            acc[hh][nf][half * 2 + 1] * inv);
            }
        }
}

// ---------------------------------------------------------------------------
extern "C" void kernel_launch(void* const* d_in, const int* in_sizes, int n_in,
                              void* d_out, int out_size)
{
    const float* x      = (const float*)d_in[0];
    const float* W_qkv  = (const float*)d_in[1];
    const float* W_v    = (const float*)d_in[2];
    const float* W_proj = (const float*)d_in[3];
    const float* b_proj = (const float*)d_in[4];
    const float* mixl   = (const float*)d_in[5];
    float* out = (float*)d_out;

    __half *px16, *pWq, *pWv, *pWp, *pYh, *pV16, *pc16, *pS4h, *pVt;
    cudaGetSymbolAddress((void**)&px16, g_x16);
    cudaGetSymbolAddress((void**)&pWq,  g_Wq16);
    cudaGetSymbolAddress((void**)&pWv,  g_Wv16);
    cudaGetSymbolAddress((void**)&pWp,  g_Wp16);
    cudaGetSymbolAddress((void**)&pYh,  g_Yh);
    cudaGetSymbolAddress((void**)&pV16, g_V16);
    cudaGetSymbolAddress((void**)&pc16, g_c16);
    cudaGetSymbolAddress((void**)&pS4h, g_S4h);
    cudaGetSymbolAddress((void**)&pVt,  g_Vt);

    static cudaStream_t s1 = nullptr;
    static cudaEvent_t evX = nullptr, evJ = nullptr;
    static bool attrDone = false;
    if (!attrDone) {
        cudaFuncSetAttribute(attn_kernel,
                             cudaFuncAttributeMaxDynamicSharedMemorySize, ATTN_SMEM);
        cudaStreamCreateWithFlags(&s1, cudaStreamNonBlocking);
        cudaEventCreateWithFlags(&evX, cudaEventDisableTiming);
        cudaEventCreateWithFlags(&evJ, cudaEventDisableTiming);
        attrDone = true;
    }

    dim3 blk(256);
    const int NX4 = B_SZ * N_SEQ * DIM / 4;
    const int NW4 = DIM * DIM / 4;
    const int NQ4 = 512 * DIM / 4;

    // ---- main: x -> fp16, then fork ---------------------------------------
    cvt16<<<(NX4 + 255) / 256, blk>>>(x, px16, NX4);
    cudaEventRecord(evX, 0);
    cudaStreamWaitEvent(s1, evX, 0);

    // ---- side stream: Wv cvt -> V -> vconvert -----------------------------
    cvt16<<<(NW4 + 255) / 256, blk, 0, s1>>>(W_v, pWv, NW4);
    gemm16<<<dim3(6, 64, 1), blk, GSMEM, s1>>>(
        px16, pWv, nullptr, pV16, nullptr, DIM, DIM, DIM, DIM, 1.0f,
        0, 0, 0, 0, 0, 1);
    vconvert<<<dim3(16, 96, 1), blk, 0, s1>>>(pV16, pVt);
    cudaEventRecord(evJ, s1);

    // ---- main: Wq cvt -> Y -> S4 -> Wp cvt --------------------------------
    cvt16<<<(NQ4 + 255) / 256, blk>>>(W_qkv, pWq, NQ4);
    gemm16<<<dim3(4, 64, 1), blk, GSMEM>>>(
        px16, pWq, nullptr, pYh, nullptr, DIM, DIM, DIM, 512, 1.0f,
        0, 0, 0, 0, 0, 1);
    gemm16<<<dim3(8, 8, B_SZ * KG), blk, GSMEM>>>(
        pYh, pYh + 256, nullptr, pS4h, nullptr, HD, 512, 512, N_SEQ, 0.125f,
        (long)N_SEQ * 512, 64, (long)N_SEQ * 512, 64, (long)N_SEQ * N_SEQ, KG);
    cvt16<<<(NW4 + 255) / 256, blk>>>(W_proj, pWp, NW4);

    // ---- join, then attn + proj on main -----------------------------------
    cudaStreamWaitEvent(0, evJ, 0);
    attn_kernel<<<dim3(16, 6, 8), blk, ATTN_SMEM>>>(pS4h, pVt, mixl, pc16);
    gemm16<<<dim3(6, 64, 1), blk, GSMEM>>>(
        pc16, pWp, out, nullptr, b_proj, DIM, DIM, DIM, DIM, 1.0f,
        0, 0, 0, 0, 0, 1);
}